// round 1
// baseline (speedup 1.0000x reference)
#include <cuda_runtime.h>
#include <math.h>

#define NROWS 4096
#define BHALF 2048
#define D     1024
#define C     12
#define BM    128
#define BK    16
#define NT    (NROWS / BM)   // 32 tiles per dim

// ---- scratch (device globals; no allocation allowed) ----
__device__ float  g_totalT[(size_t)D * NROWS];   // 16MB, [k][i] = total[i][k]
__device__ float  g_z[NROWS * C];                // signed, masked, normalized class vectors
__device__ float  g_sq[NROWS];                   // row sum of squares
__device__ float  g_sfac[C], g_tfac[C];          // per-class factors (tfac includes the minus sign)
__device__ double g_sumsq, g_colsq, g_loss;
__device__ float  g_coef;                        // -1/(16*bw*ln2) for exp2f

// ---------------------------------------------------------------- init
__global__ void k_init() {
    g_sumsq = 0.0; g_colsq = 0.0; g_loss = 0.0;
}

// ------------------------------------------------------- class statistics
__global__ void k_stats(const float* __restrict__ sl, const float* __restrict__ tl) {
    __shared__ float ssum[C], tsum[C];
    __shared__ int   spres[C], tpres[C];
    int tid = threadIdx.x;
    if (tid < C) { ssum[tid] = 0.f; tsum[tid] = 0.f; spres[tid] = 0; tpres[tid] = 0; }
    __syncthreads();
    for (int r = tid; r < BHALF; r += blockDim.x) {
        float best = -INFINITY; int arg = 0;
        #pragma unroll
        for (int c = 0; c < C; c++) {
            float v = sl[r * C + c];
            atomicAdd(&ssum[c], v);
            if (v > best) { best = v; arg = c; }     // first max == jnp.argmax
        }
        spres[arg] = 1;
        best = -INFINITY; arg = 0;
        #pragma unroll
        for (int c = 0; c < C; c++) {
            float v = tl[r * C + c];
            atomicAdd(&tsum[c], v);
            if (v > best) { best = v; arg = c; }
        }
        tpres[arg] = 1;
    }
    __syncthreads();
    if (tid < C) {
        bool common = (spres[tid] != 0) && (tpres[tid] != 0);
        g_sfac[tid] = (common && ssum[tid] > 0.f) ?  1.f / ssum[tid] : 0.f;
        g_tfac[tid] = (common && tsum[tid] > 0.f) ? -1.f / tsum[tid] : 0.f;
    }
}

// -------------------------------------------------------------- z vectors
__global__ void k_z(const float* __restrict__ sl, const float* __restrict__ tl) {
    int i = blockIdx.x * blockDim.x + threadIdx.x;
    if (i >= NROWS) return;
    if (i < BHALF) {
        #pragma unroll
        for (int c = 0; c < C; c++) g_z[i * C + c] = sl[i * C + c] * g_sfac[c];
    } else {
        #pragma unroll
        for (int c = 0; c < C; c++) g_z[i * C + c] = tl[(i - BHALF) * C + c] * g_tfac[c];
    }
}

// ------------------------------------------------------------- transpose
// totalT[k][i] = total[i][k]   (total = concat(source, target))
__global__ void k_transpose(const float* __restrict__ src, const float* __restrict__ tgt) {
    __shared__ float tile[32][33];
    int k0 = blockIdx.x * 32;
    int i0 = blockIdx.y * 32;
    #pragma unroll
    for (int s = 0; s < 32; s += 8) {
        int ii = threadIdx.y + s;
        int i  = i0 + ii;
        const float* p = (i < BHALF) ? (src + (size_t)i * D) : (tgt + (size_t)(i - BHALF) * D);
        tile[ii][threadIdx.x] = p[k0 + threadIdx.x];
    }
    __syncthreads();
    #pragma unroll
    for (int s = 0; s < 32; s += 8) {
        int kk = threadIdx.y + s;
        g_totalT[(size_t)(k0 + kk) * NROWS + i0 + threadIdx.x] = tile[threadIdx.x][kk];
    }
}

// -------------------------------------------------- row sum-of-squares + Σsq
__global__ void k_sq(const float* __restrict__ src, const float* __restrict__ tgt) {
    __shared__ float sred[256];
    int i = blockIdx.x;
    const float* p = (i < BHALF) ? (src + (size_t)i * D) : (tgt + (size_t)(i - BHALF) * D);
    float s = 0.f;
    for (int k = threadIdx.x; k < D; k += 256) { float v = p[k]; s += v * v; }
    sred[threadIdx.x] = s;
    __syncthreads();
    for (int o = 128; o > 0; o >>= 1) {
        if (threadIdx.x < o) sred[threadIdx.x] += sred[threadIdx.x + o];
        __syncthreads();
    }
    if (threadIdx.x == 0) {
        g_sq[i] = sred[0];
        atomicAdd(&g_sumsq, (double)sred[0]);
    }
}

// ------------------------------------------------- ||colsum||^2 reduction
__global__ void k_colsq() {
    __shared__ float sred[256];
    int k = blockIdx.x;
    const float* row = g_totalT + (size_t)k * NROWS;
    float s = 0.f;
    for (int j = threadIdx.x; j < NROWS; j += 256) s += row[j];
    sred[threadIdx.x] = s;
    __syncthreads();
    for (int o = 128; o > 0; o >>= 1) {
        if (threadIdx.x < o) sred[threadIdx.x] += sred[threadIdx.x + o];
        __syncthreads();
    }
    if (threadIdx.x == 0) {
        double cs = (double)sred[0];
        atomicAdd(&g_colsq, cs * cs);
    }
}

// ------------------------------------------------------------- bandwidth
__global__ void k_bw() {
    const double n = (double)NROWS;
    double sum_l2 = 2.0 * n * g_sumsq - 2.0 * g_colsq;       // clamp correction ~1e-10 rel
    double bw = sum_l2 / (n * n - n) / 4.0;                  // / KERNEL_MUL^(KERNEL_NUM/2)
    g_coef = (float)(-1.0 / (16.0 * bw * 0.6931471805599453));
}

// --------------------------------------------------- fused GEMM + MMD loss
__global__ __launch_bounds__(256, 2) void k_mmd() {
    // triangular tile decode: bj >= bi
    int L = blockIdx.x;
    int bi = 0;
    while (L >= NT - bi) { L -= NT - bi; bi++; }
    int bj = bi + L;

    __shared__ __align__(16) float As[2][BK][BM];
    __shared__ __align__(16) float Bs[2][BK][BM];
    __shared__ float sqA[BM], sqB[BM];
    __shared__ float red[8];

    const int tid = threadIdx.x;
    const int tx  = tid & 15;
    const int ty  = tid >> 4;
    const int rowA = bi * BM;
    const int rowB = bj * BM;

    float acc[8][8];
    #pragma unroll
    for (int u = 0; u < 8; u++)
        #pragma unroll
        for (int v = 0; v < 8; v++) acc[u][v] = 0.f;

    // loader mapping: 512 float4 per operand tile, 2 per thread
    const int lkk0 = tid >> 5;          // 0..7
    const int lc4  = (tid & 31) << 2;   // 0..124 step 4

    // prologue: stage tile 0
    {
        #pragma unroll
        for (int r = 0; r < 2; r++) {
            int kk = lkk0 + 8 * r;
            float4 a = *(const float4*)&g_totalT[(size_t)kk * NROWS + rowA + lc4];
            float4 b = *(const float4*)&g_totalT[(size_t)kk * NROWS + rowB + lc4];
            *(float4*)&As[0][kk][lc4] = a;
            *(float4*)&Bs[0][kk][lc4] = b;
        }
    }

    int buf = 0;
    for (int kt = 0; kt < D / BK; kt++) {
        __syncthreads();
        int k0n = (kt + 1) * BK;
        float4 rA[2], rB[2];
        if (k0n < D) {
            #pragma unroll
            for (int r = 0; r < 2; r++) {
                int kk = lkk0 + 8 * r;
                rA[r] = *(const float4*)&g_totalT[(size_t)(k0n + kk) * NROWS + rowA + lc4];
                rB[r] = *(const float4*)&g_totalT[(size_t)(k0n + kk) * NROWS + rowB + lc4];
            }
        }
        #pragma unroll
        for (int kk = 0; kk < BK; kk++) {
            float a[8], b[8];
            *(float4*)&a[0] = *(const float4*)&As[buf][kk][ty * 8];
            *(float4*)&a[4] = *(const float4*)&As[buf][kk][ty * 8 + 4];
            *(float4*)&b[0] = *(const float4*)&Bs[buf][kk][tx * 8];
            *(float4*)&b[4] = *(const float4*)&Bs[buf][kk][tx * 8 + 4];
            #pragma unroll
            for (int u = 0; u < 8; u++)
                #pragma unroll
                for (int v = 0; v < 8; v++)
                    acc[u][v] = fmaf(a[u], b[v], acc[u][v]);
        }
        if (k0n < D) {
            #pragma unroll
            for (int r = 0; r < 2; r++) {
                int kk = lkk0 + 8 * r;
                *(float4*)&As[buf ^ 1][kk][lc4] = rA[r];
                *(float4*)&Bs[buf ^ 1][kk][lc4] = rB[r];
            }
        }
        buf ^= 1;
    }

    // ---- epilogue: l2 -> 5-kernel sum -> rank-12 weight -> loss partial ----
    __syncthreads();                    // done reading As/Bs; reuse as z staging
    float* zA = (float*)As;             // [128][12]
    float* zB = zA + BM * C;
    for (int t = tid; t < BM * C; t += 256) {
        zA[t] = g_z[(rowA + t / C) * C + (t % C)];
        zB[t] = g_z[(rowB + t / C) * C + (t % C)];
    }
    if (tid < BM) { sqA[tid] = g_sq[rowA + tid]; sqB[tid] = g_sq[rowB + tid]; }
    __syncthreads();

    const float coef  = g_coef;
    const float scale = (bi == bj) ? 1.f : 2.f;
    float lsum = 0.f;
    #pragma unroll
    for (int u = 0; u < 8; u++) {
        int i = ty * 8 + u;
        float zi[C];
        #pragma unroll
        for (int c = 0; c < C; c++) zi[c] = zA[i * C + c];
        float sqi = sqA[i];
        #pragma unroll
        for (int v = 0; v < 8; v++) {
            int j = tx * 8 + v;
            float l2 = fmaxf(sqi + sqB[j] - 2.f * acc[u][v], 0.f);
            float e  = exp2f(l2 * coef);            // exp(-l2/(16*bw))
            float e2 = e * e, e4 = e2 * e2, e8 = e4 * e4, e16 = e8 * e8;
            float ks = e + e2 + e4 + e8 + e16;      // sum over 5 bandwidths
            float w = 0.f;
            #pragma unroll
            for (int c = 0; c < C; c++) w = fmaf(zi[c], zB[j * C + c], w);
            lsum = fmaf(w, ks, lsum);
        }
    }
    lsum *= scale;

    // block reduce
    #pragma unroll
    for (int o = 16; o > 0; o >>= 1) lsum += __shfl_xor_sync(0xffffffffu, lsum, o);
    if ((tid & 31) == 0) red[tid >> 5] = lsum;
    __syncthreads();
    if (tid == 0) {
        float s = 0.f;
        #pragma unroll
        for (int w = 0; w < 8; w++) s += red[w];
        atomicAdd(&g_loss, (double)s);
    }
}

// ---------------------------------------------------------------- output
__global__ void k_out(float* out) {
    float f = (float)(g_loss / 12.0);   // the 1/n_class weight factor
    if (!isfinite(f)) f = 0.f;          // NaN guard from reference
    out[0] = f;
}

// ---------------------------------------------------------------- launch
extern "C" void kernel_launch(void* const* d_in, const int* in_sizes, int n_in,
                              void* d_out, int out_size) {
    const float* src = (const float*)d_in[0];   // source [2048,1024]
    const float* tgt = (const float*)d_in[1];   // target [2048,1024]
    const float* sl  = (const float*)d_in[2];   // source_label [2048,12]
    const float* tl  = (const float*)d_in[3];   // target_logits [2048,12]
    float* out = (float*)d_out;

    k_init<<<1, 1>>>();
    k_stats<<<1, 256>>>(sl, tl);
    k_z<<<(NROWS + 255) / 256, 256>>>(sl, tl);
    k_transpose<<<dim3(D / 32, NROWS / 32), dim3(32, 8)>>>(src, tgt);
    k_sq<<<NROWS, 256>>>(src, tgt);
    k_colsq<<<D, 256>>>();
    k_bw<<<1, 1>>>();
    k_mmd<<<NT * (NT + 1) / 2, 256>>>();
    k_out<<<1, 1>>>(out);
}

// round 4
// speedup vs baseline: 1.7053x; 1.7053x over previous
#include <cuda_runtime.h>
#include <cuda_fp16.h>
#include <math.h>
#include <stdint.h>

#define NROWS 4096
#define BHALF 2048
#define D     1024
#define C     12
#define BM    128
#define NT    (NROWS / BM)          // 32
#define NTILES (NT * (NT + 1) / 2)  // 528
#define KCH   32                    // K elements per staged chunk
#define NCH   (D / KCH)             // 32 chunks
#define RSTR  40                    // smem row stride in halves (32 + 8 pad) = 20 u32 words

// smem layout (bytes), per array: 2 bufs x 128 rows x 40 halves = 20480B
#define ARR_BYTES (2 * BM * RSTR * 2)
#define OFF_AHI 0
#define OFF_ALO (1 * ARR_BYTES)
#define OFF_BHI (2 * ARR_BYTES)
#define OFF_BLO (3 * ARR_BYTES)
#define OFF_ZB  (4 * ARR_BYTES)            // 81920
#define OFF_SQB (OFF_ZB + BM * C * 4)      // +6144
#define SMEM_REQ (OFF_SQB + BM * 4 + 256)  // ~88.9KB

// ---- scratch (device globals; no allocation allowed) ----
__device__ __half g_hi[(size_t)NROWS * D];
__device__ __half g_lo[(size_t)NROWS * D];
__device__ float  g_z[NROWS * C];
__device__ float  g_sq[NROWS];
__device__ float  g_colsum[D];
__device__ float  g_sfac[C], g_tfac[C];
__device__ double g_sumsq, g_colsq, g_loss;
__device__ float  g_coef;

static __device__ __forceinline__ uint32_t s2u(const void* p) {
    uint32_t a;
    asm("{ .reg .u64 t; cvta.to.shared.u64 t, %1; cvt.u32.u64 %0, t; }" : "=r"(a) : "l"(p));
    return a;
}

#define CP_ASYNC16(dst, src) \
    asm volatile("cp.async.cg.shared.global [%0], [%1], 16;" :: "r"(dst), "l"(src))
#define CP_COMMIT()  asm volatile("cp.async.commit_group;" ::: "memory")
#define CP_WAIT1()   asm volatile("cp.async.wait_group 1;" ::: "memory")
#define CP_WAIT0()   asm volatile("cp.async.wait_group 0;" ::: "memory")

static __device__ __forceinline__ void mma_f16(float* c, const uint32_t* a, const uint32_t* b) {
    asm volatile(
        "mma.sync.aligned.m16n8k16.row.col.f32.f16.f16.f32 "
        "{%0,%1,%2,%3}, {%4,%5,%6,%7}, {%8,%9}, {%0,%1,%2,%3};"
        : "+f"(c[0]), "+f"(c[1]), "+f"(c[2]), "+f"(c[3])
        : "r"(a[0]), "r"(a[1]), "r"(a[2]), "r"(a[3]), "r"(b[0]), "r"(b[1]));
}

// ================================================================ small kernels
__global__ void k_init() {
    int t = threadIdx.x;
    if (t == 0) { g_sumsq = 0.0; g_colsq = 0.0; g_loss = 0.0; }
    for (int c = t; c < D; c += 256) g_colsum[c] = 0.f;
}

// split inputs into hi/lo halves, concatenated layout
__global__ void k_split(const float* __restrict__ src, const float* __restrict__ tgt) {
    size_t q = (size_t)blockIdx.x * 256 + threadIdx.x;       // float4 index
    size_t e = q * 4;
    size_t row = e >> 10;
    const float* p = (row < BHALF) ? src : (tgt - (size_t)BHALF * D);
    float4 v = *(const float4*)(p + e);
    __half h[4]; __half l[4];
    float vv[4] = {v.x, v.y, v.z, v.w};
    #pragma unroll
    for (int i = 0; i < 4; i++) {
        h[i] = __float2half_rn(vv[i]);
        l[i] = __float2half_rn(vv[i] - __half2float(h[i]));
    }
    *(uint2*)&g_hi[e] = *(uint2*)h;
    *(uint2*)&g_lo[e] = *(uint2*)l;
}

__global__ void k_stats(const float* __restrict__ sl, const float* __restrict__ tl) {
    __shared__ float ssum[C], tsum[C];
    __shared__ int   spres[C], tpres[C];
    int tid = threadIdx.x;
    if (tid < C) { ssum[tid] = 0.f; tsum[tid] = 0.f; spres[tid] = 0; tpres[tid] = 0; }
    __syncthreads();
    for (int r = tid; r < BHALF; r += blockDim.x) {
        float best = -INFINITY; int arg = 0;
        #pragma unroll
        for (int c = 0; c < C; c++) {
            float v = sl[r * C + c];
            atomicAdd(&ssum[c], v);
            if (v > best) { best = v; arg = c; }
        }
        spres[arg] = 1;
        best = -INFINITY; arg = 0;
        #pragma unroll
        for (int c = 0; c < C; c++) {
            float v = tl[r * C + c];
            atomicAdd(&tsum[c], v);
            if (v > best) { best = v; arg = c; }
        }
        tpres[arg] = 1;
    }
    __syncthreads();
    if (tid < C) {
        bool common = (spres[tid] != 0) && (tpres[tid] != 0);
        g_sfac[tid] = (common && ssum[tid] > 0.f) ?  1.f / ssum[tid] : 0.f;
        g_tfac[tid] = (common && tsum[tid] > 0.f) ? -1.f / tsum[tid] : 0.f;
    }
}

__global__ void k_z(const float* __restrict__ sl, const float* __restrict__ tl) {
    int i = blockIdx.x * blockDim.x + threadIdx.x;
    if (i >= NROWS) return;
    if (i < BHALF) {
        #pragma unroll
        for (int c = 0; c < C; c++) g_z[i * C + c] = sl[i * C + c] * g_sfac[c];
    } else {
        #pragma unroll
        for (int c = 0; c < C; c++) g_z[i * C + c] = tl[(i - BHALF) * C + c] * g_tfac[c];
    }
}

__global__ void k_sq(const float* __restrict__ src, const float* __restrict__ tgt) {
    __shared__ float sred[256];
    int i = blockIdx.x;
    const float* p = (i < BHALF) ? (src + (size_t)i * D) : (tgt + (size_t)(i - BHALF) * D);
    float s = 0.f;
    for (int k = threadIdx.x; k < D; k += 256) { float v = p[k]; s += v * v; }
    sred[threadIdx.x] = s;
    __syncthreads();
    for (int o = 128; o > 0; o >>= 1) {
        if (threadIdx.x < o) sred[threadIdx.x] += sred[threadIdx.x + o];
        __syncthreads();
    }
    if (threadIdx.x == 0) {
        g_sq[i] = sred[0];
        atomicAdd(&g_sumsq, (double)sred[0]);
    }
}

__global__ void k_colsum(const float* __restrict__ src, const float* __restrict__ tgt) {
    int r0 = blockIdx.x * 32;
    const float* p = (r0 < BHALF) ? (src + (size_t)r0 * D) : (tgt + (size_t)(r0 - BHALF) * D);
    for (int c = threadIdx.x; c < D; c += 256) {
        float s = 0.f;
        #pragma unroll 8
        for (int r = 0; r < 32; r++) s += p[(size_t)r * D + c];
        atomicAdd(&g_colsum[c], s);
    }
}

__global__ void k_colsq() {
    __shared__ double sr[256];
    double s = 0.0;
    for (int c = threadIdx.x; c < D; c += 256) { double v = (double)g_colsum[c]; s += v * v; }
    sr[threadIdx.x] = s;
    __syncthreads();
    for (int o = 128; o > 0; o >>= 1) {
        if (threadIdx.x < o) sr[threadIdx.x] += sr[threadIdx.x + o];
        __syncthreads();
    }
    if (threadIdx.x == 0) g_colsq = sr[0];
}

__global__ void k_bw() {
    const double n = (double)NROWS;
    double sum_l2 = 2.0 * n * g_sumsq - 2.0 * g_colsq;
    double bw = sum_l2 / (n * n - n) / 4.0;
    g_coef = (float)(-1.0 / (16.0 * bw * 0.6931471805599453));
}

// ===================================== fp16-split mma.sync fused GEMM + MMD
__global__ __launch_bounds__(256) void k_mmd() {
    extern __shared__ __align__(16) unsigned char sm[];
    float* zB  = (float*)(sm + OFF_ZB);
    float* sqB = (float*)(sm + OFF_SQB);
    __shared__ float red[8];

    const int tid = threadIdx.x, wid = tid >> 5, lane = tid & 31;
    const int wm = wid >> 1, wn = wid & 1;               // warp grid 4x2
    const int gq = lane >> 2, gr = lane & 3;             // group / thread-in-quad

    // triangular tile decode: bj >= bi
    int L = blockIdx.x, bi = 0;
    while (L >= NT - bi) { L -= NT - bi; bi++; }
    int bj = bi + L;
    const int rowA = bi * BM, rowB = bj * BM;

    // stage z/sq for B rows
    for (int t = tid; t < BM * C; t += 256)
        zB[t] = g_z[(size_t)(rowB + t / C) * C + (t % C)];
    if (tid < BM) sqB[tid] = g_sq[rowB + tid];

    float acc[2][8][4];
    #pragma unroll
    for (int m = 0; m < 2; m++)
        #pragma unroll
        for (int n = 0; n < 8; n++)
            #pragma unroll
            for (int r = 0; r < 4; r++) acc[m][n][r] = 0.f;

    // staging: per array 512 x 16B tasks, 2 per thread
    const int sr0 = tid >> 2,         sg0 = tid & 3;
    const int sr1 = (tid + 256) >> 2, sg1 = tid & 3;
    const uint32_t smU = s2u(sm);
    const size_t gA = (size_t)rowA * D, gB = (size_t)rowB * D;

    #define STAGE(buf, c) do {                                                         \
        const uint32_t bo = (buf) * (BM * RSTR * 2);                                   \
        const size_t ko = (size_t)(c) * KCH;                                           \
        CP_ASYNC16(smU + OFF_AHI + bo + (sr0 * RSTR + sg0 * 8) * 2, g_hi + gA + sr0 * D + ko + sg0 * 8); \
        CP_ASYNC16(smU + OFF_AHI + bo + (sr1 * RSTR + sg1 * 8) * 2, g_hi + gA + sr1 * D + ko + sg1 * 8); \
        CP_ASYNC16(smU + OFF_ALO + bo + (sr0 * RSTR + sg0 * 8) * 2, g_lo + gA + sr0 * D + ko + sg0 * 8); \
        CP_ASYNC16(smU + OFF_ALO + bo + (sr1 * RSTR + sg1 * 8) * 2, g_lo + gA + sr1 * D + ko + sg1 * 8); \
        CP_ASYNC16(smU + OFF_BHI + bo + (sr0 * RSTR + sg0 * 8) * 2, g_hi + gB + sr0 * D + ko + sg0 * 8); \
        CP_ASYNC16(smU + OFF_BHI + bo + (sr1 * RSTR + sg1 * 8) * 2, g_hi + gB + sr1 * D + ko + sg1 * 8); \
        CP_ASYNC16(smU + OFF_BLO + bo + (sr0 * RSTR + sg0 * 8) * 2, g_lo + gB + sr0 * D + ko + sg0 * 8); \
        CP_ASYNC16(smU + OFF_BLO + bo + (sr1 * RSTR + sg1 * 8) * 2, g_lo + gB + sr1 * D + ko + sg1 * 8); \
        CP_COMMIT();                                                                   \
    } while (0)

    STAGE(0, 0);

    for (int c = 0; c < NCH; c++) {
        const int buf = c & 1;
        if (c + 1 < NCH) { STAGE(buf ^ 1, c + 1); CP_WAIT1(); }
        else             { CP_WAIT0(); }
        __syncthreads();

        const uint32_t* Ah = (const uint32_t*)(sm + OFF_AHI + buf * (BM * RSTR * 2));
        const uint32_t* Al = (const uint32_t*)(sm + OFF_ALO + buf * (BM * RSTR * 2));
        const uint32_t* Bh = (const uint32_t*)(sm + OFF_BHI + buf * (BM * RSTR * 2));
        const uint32_t* Bl = (const uint32_t*)(sm + OFF_BLO + buf * (BM * RSTR * 2));

        #pragma unroll
        for (int ks = 0; ks < 2; ks++) {
            const int wb = ks * 8 + gr;                  // u32 word index (row has 20 words)
            uint32_t ahi[2][4], alo[2][4];
            #pragma unroll
            for (int m = 0; m < 2; m++) {
                const int ar = wm * 32 + m * 16 + gq;
                ahi[m][0] = Ah[ar * (RSTR / 2) + wb];
                ahi[m][1] = Ah[(ar + 8) * (RSTR / 2) + wb];
                ahi[m][2] = Ah[ar * (RSTR / 2) + wb + 4];
                ahi[m][3] = Ah[(ar + 8) * (RSTR / 2) + wb + 4];
                alo[m][0] = Al[ar * (RSTR / 2) + wb];
                alo[m][1] = Al[(ar + 8) * (RSTR / 2) + wb];
                alo[m][2] = Al[ar * (RSTR / 2) + wb + 4];
                alo[m][3] = Al[(ar + 8) * (RSTR / 2) + wb + 4];
            }
            #pragma unroll
            for (int n = 0; n < 8; n++) {
                const int br = wn * 64 + n * 8 + gq;
                uint32_t bhi[2], blo[2];
                bhi[0] = Bh[br * (RSTR / 2) + wb];
                bhi[1] = Bh[br * (RSTR / 2) + wb + 4];
                blo[0] = Bl[br * (RSTR / 2) + wb];
                blo[1] = Bl[br * (RSTR / 2) + wb + 4];
                mma_f16(acc[0][n], ahi[0], bhi);
                mma_f16(acc[1][n], ahi[1], bhi);
                mma_f16(acc[0][n], ahi[0], blo);
                mma_f16(acc[1][n], ahi[1], blo);
                mma_f16(acc[0][n], alo[0], bhi);
                mma_f16(acc[1][n], alo[1], bhi);
            }
        }
        __syncthreads();
    }

    // -------- epilogue: l2 -> 5-kernel sum -> rank-12 weight (fp32) --------
    const float coef = g_coef;
    float lsum = 0.f;
    #pragma unroll
    for (int m = 0; m < 2; m++) {
        #pragma unroll
        for (int h = 0; h < 2; h++) {
            const int i = rowA + wm * 32 + m * 16 + gq + 8 * h;
            const float sqi = g_sq[i];
            float zi[C];
            #pragma unroll
            for (int cc = 0; cc < C; cc++) zi[cc] = g_z[(size_t)i * C + cc];
            #pragma unroll
            for (int n = 0; n < 8; n++) {
                #pragma unroll
                for (int p = 0; p < 2; p++) {
                    const int j = wn * 64 + n * 8 + 2 * gr + p;
                    const float gv = acc[m][n][2 * h + p];
                    float l2 = fmaxf(fmaf(-2.f, gv, sqi + sqB[j]), 0.f);
                    float e;
                    asm("ex2.approx.ftz.f32 %0, %1;" : "=f"(e) : "f"(l2 * coef));
                    float e2 = e * e, e4 = e2 * e2, e8 = e4 * e4, e16 = e8 * e8;
                    float ks5 = e + e2 + e4 + e8 + e16;
                    float w = 0.f;
                    #pragma unroll
                    for (int cc = 0; cc < C; cc++) w = fmaf(zi[cc], zB[j * C + cc], w);
                    lsum = fmaf(w, ks5, lsum);
                }
            }
        }
    }
    if (bi != bj) lsum *= 2.f;

    #pragma unroll
    for (int o = 16; o > 0; o >>= 1) lsum += __shfl_xor_sync(0xffffffffu, lsum, o);
    if (lane == 0) red[wid] = lsum;
    __syncthreads();
    if (tid == 0) {
        float s = 0.f;
        #pragma unroll
        for (int w = 0; w < 8; w++) s += red[w];
        atomicAdd(&g_loss, (double)s);
    }
}

__global__ void k_out(float* out) {
    float f = (float)(g_loss / 12.0);
    if (!isfinite(f)) f = 0.f;
    out[0] = f;
}

// ================================================================ launch
extern "C" void kernel_launch(void* const* d_in, const int* in_sizes, int n_in,
                              void* d_out, int out_size) {
    const float* src = (const float*)d_in[0];
    const float* tgt = (const float*)d_in[1];
    const float* sl  = (const float*)d_in[2];
    const float* tl  = (const float*)d_in[3];
    float* out = (float*)d_out;

    cudaFuncSetAttribute(k_mmd, cudaFuncAttributeMaxDynamicSharedMemorySize, SMEM_REQ);

    k_init<<<1, 256>>>();
    k_split<<<(NROWS * D / 4) / 256, 256>>>(src, tgt);
    k_stats<<<1, 256>>>(sl, tl);
    k_z<<<(NROWS + 255) / 256, 256>>>(sl, tl);
    k_sq<<<NROWS, 256>>>(src, tgt);
    k_colsum<<<NROWS / 32, 256>>>(src, tgt);
    k_colsq<<<1, 256>>>();
    k_bw<<<1, 1>>>();
    k_mmd<<<NTILES, 256, SMEM_REQ>>>();
    k_out<<<1, 1>>>(out);
}

// round 5
// speedup vs baseline: 1.7523x; 1.0275x over previous
#include <cuda_runtime.h>
#include <cuda_fp16.h>
#include <math.h>
#include <stdint.h>

#define NROWS 4096
#define BHALF 2048
#define D     1024
#define C     12
#define BM    128
#define NT    (NROWS / BM)          // 32
#define NTILES (NT * (NT + 1) / 2)  // 528
#define KCH   32                    // K elements per staged chunk
#define NCH   (D / KCH)             // 32 chunks
#define RSTR  40                    // smem row stride in halves (32 + 8 pad)

#define ARR_BYTES (2 * BM * RSTR * 2)      // per array: 2 bufs x 128 x 40 halves
#define OFF_AHI 0
#define OFF_ALO (1 * ARR_BYTES)
#define OFF_BHI (2 * ARR_BYTES)
#define OFF_BLO (3 * ARR_BYTES)
#define OFF_ZB  (4 * ARR_BYTES)
#define OFF_SQB (OFF_ZB + BM * C * 4)
#define SMEM_REQ (OFF_SQB + BM * 4 + 256)

// ---- scratch (device globals; no allocation allowed) ----
__device__ __half g_hi[(size_t)NROWS * D];
__device__ __half g_lo[(size_t)NROWS * D];
__device__ float  g_z[NROWS * C];
__device__ float  g_sq[NROWS];
__device__ float  g_colsum[D];
__device__ float  g_sfac[C], g_tfac[C];
__device__ double g_sumsq, g_loss;
__device__ float  g_coef;
__device__ int    g_cnt;

static __device__ __forceinline__ uint32_t s2u(const void* p) {
    uint32_t a;
    asm("{ .reg .u64 t; cvta.to.shared.u64 t, %1; cvt.u32.u64 %0, t; }" : "=r"(a) : "l"(p));
    return a;
}

#define CP_ASYNC16(dst, src) \
    asm volatile("cp.async.cg.shared.global [%0], [%1], 16;" :: "r"(dst), "l"(src))
#define CP_COMMIT()  asm volatile("cp.async.commit_group;" ::: "memory")
#define CP_WAIT1()   asm volatile("cp.async.wait_group 1;" ::: "memory")
#define CP_WAIT0()   asm volatile("cp.async.wait_group 0;" ::: "memory")

#define LDSM4(r, a) \
    asm volatile("ldmatrix.sync.aligned.m8n8.x4.shared.b16 {%0,%1,%2,%3}, [%4];" \
        : "=r"((r)[0]), "=r"((r)[1]), "=r"((r)[2]), "=r"((r)[3]) : "r"(a))

static __device__ __forceinline__ void mma_f16(float* c, const uint32_t* a,
                                               uint32_t b0, uint32_t b1) {
    asm volatile(
        "mma.sync.aligned.m16n8k16.row.col.f32.f16.f16.f32 "
        "{%0,%1,%2,%3}, {%4,%5,%6,%7}, {%8,%9}, {%0,%1,%2,%3};"
        : "+f"(c[0]), "+f"(c[1]), "+f"(c[2]), "+f"(c[3])
        : "r"(a[0]), "r"(a[1]), "r"(a[2]), "r"(a[3]), "r"(b0), "r"(b1));
}

// ================================================ launch 0: split + zero
__global__ void k_split(const float* __restrict__ src, const float* __restrict__ tgt) {
    if (blockIdx.x == 0) {
        if (threadIdx.x == 0) { g_sumsq = 0.0; g_loss = 0.0; g_cnt = 0; }
        for (int c = threadIdx.x; c < D; c += 256) g_colsum[c] = 0.f;
    }
    size_t q = (size_t)blockIdx.x * 256 + threadIdx.x;
    size_t e = q * 4;
    size_t row = e >> 10;
    const float* p = (row < BHALF) ? src : (tgt - (size_t)BHALF * D);
    float4 v = *(const float4*)(p + e);
    __half h[4]; __half l[4];
    float vv[4] = {v.x, v.y, v.z, v.w};
    #pragma unroll
    for (int i = 0; i < 4; i++) {
        h[i] = __float2half_rn(vv[i]);
        l[i] = __float2half_rn(vv[i] - __half2float(h[i]));
    }
    *(uint2*)&g_hi[e] = *(uint2*)h;
    *(uint2*)&g_lo[e] = *(uint2*)l;
}

// ================================================ launch 1: class stats
__global__ void k_stats(const float* __restrict__ sl, const float* __restrict__ tl) {
    __shared__ float ssum[C], tsum[C];
    __shared__ int   spres[C], tpres[C];
    int tid = threadIdx.x;
    if (tid < C) { ssum[tid] = 0.f; tsum[tid] = 0.f; spres[tid] = 0; tpres[tid] = 0; }
    __syncthreads();
    for (int r = tid; r < BHALF; r += blockDim.x) {
        float best = -INFINITY; int arg = 0;
        #pragma unroll
        for (int c = 0; c < C; c++) {
            float v = sl[r * C + c];
            atomicAdd(&ssum[c], v);
            if (v > best) { best = v; arg = c; }
        }
        spres[arg] = 1;
        best = -INFINITY; arg = 0;
        #pragma unroll
        for (int c = 0; c < C; c++) {
            float v = tl[r * C + c];
            atomicAdd(&tsum[c], v);
            if (v > best) { best = v; arg = c; }
        }
        tpres[arg] = 1;
    }
    __syncthreads();
    if (tid < C) {
        bool common = (spres[tid] != 0) && (tpres[tid] != 0);
        g_sfac[tid] = (common && ssum[tid] > 0.f) ?  1.f / ssum[tid] : 0.f;
        g_tfac[tid] = (common && tsum[tid] > 0.f) ? -1.f / tsum[tid] : 0.f;
    }
}

// ====================== launch 2: z + row-sq + colsum + (last block) bandwidth
__global__ void k_prep(const float* __restrict__ src, const float* __restrict__ tgt,
                       const float* __restrict__ sl, const float* __restrict__ tl) {
    const int tid = threadIdx.x, lane = tid & 31, w = tid >> 5;
    const int r0 = blockIdx.x * 32;
    const float* base = (r0 < BHALF) ? src + (size_t)r0 * D : tgt + (size_t)(r0 - BHALF) * D;

    // z vectors
    for (int t = tid; t < 32 * C; t += 256) {
        int r = r0 + t / C, c = t % C;
        float v = (r < BHALF) ? sl[(size_t)r * C + c] * g_sfac[c]
                              : tl[(size_t)(r - BHALF) * C + c] * g_tfac[c];
        g_z[(size_t)r * C + c] = v;
    }
    // per-row sum of squares (warp per row)
    #pragma unroll
    for (int t = 0; t < 4; t++) {
        int rr = w + 8 * t;
        const float* p = base + (size_t)rr * D;
        float s = 0.f;
        #pragma unroll
        for (int j = 0; j < 8; j++) {
            float4 v = *(const float4*)(p + lane * 4 + 128 * j);
            s += v.x * v.x + v.y * v.y + v.z * v.z + v.w * v.w;
        }
        #pragma unroll
        for (int o = 16; o > 0; o >>= 1) s += __shfl_xor_sync(0xffffffffu, s, o);
        if (lane == 0) { g_sq[r0 + rr] = s; atomicAdd(&g_sumsq, (double)s); }
    }
    // column-sum partials
    {
        int c4 = tid * 4;
        float4 a = {0.f, 0.f, 0.f, 0.f};
        for (int rr = 0; rr < 32; rr++) {
            float4 v = *(const float4*)(base + (size_t)rr * D + c4);
            a.x += v.x; a.y += v.y; a.z += v.z; a.w += v.w;
        }
        atomicAdd(&g_colsum[c4 + 0], a.x);
        atomicAdd(&g_colsum[c4 + 1], a.y);
        atomicAdd(&g_colsum[c4 + 2], a.z);
        atomicAdd(&g_colsum[c4 + 3], a.w);
    }
    __threadfence();
    __syncthreads();
    __shared__ int lastf;
    if (tid == 0) lastf = (atomicAdd(&g_cnt, 1) == gridDim.x - 1) ? 1 : 0;
    __syncthreads();
    if (lastf) {
        __shared__ double sr[256];
        double s = 0.0;
        for (int c = tid; c < D; c += 256) { double v = (double)g_colsum[c]; s += v * v; }
        sr[tid] = s;
        __syncthreads();
        for (int o = 128; o > 0; o >>= 1) {
            if (tid < o) sr[tid] += sr[tid + o];
            __syncthreads();
        }
        if (tid == 0) {
            const double n = (double)NROWS;
            double sum_l2 = 2.0 * n * g_sumsq - 2.0 * sr[0];
            double bw = sum_l2 / (n * n - n) / 4.0;
            g_coef = (float)(-1.0 / (16.0 * bw * 0.6931471805599453));
        }
    }
}

// ============ launch 3: fp16-split mma.sync fused GEMM + MMD (profiled slot)
__global__ __launch_bounds__(256, 2) void k_mmd() {
    extern __shared__ __align__(16) unsigned char sm[];
    float* zB  = (float*)(sm + OFF_ZB);
    float* sqB = (float*)(sm + OFF_SQB);
    __shared__ float red[8];

    const int tid = threadIdx.x, wid = tid >> 5, lane = tid & 31;
    const int wm = wid >> 1, wn = wid & 1;               // warp grid 4x2
    const int gq = lane >> 2, gr = lane & 3;

    int L = blockIdx.x, bi = 0;
    while (L >= NT - bi) { L -= NT - bi; bi++; }
    int bj = bi + L;
    const int rowA = bi * BM, rowB = bj * BM;

    for (int t = tid; t < BM * C; t += 256)
        zB[t] = g_z[(size_t)(rowB + t / C) * C + (t % C)];
    if (tid < BM) sqB[tid] = g_sq[rowB + tid];

    float acc[2][8][4];
    #pragma unroll
    for (int m = 0; m < 2; m++)
        #pragma unroll
        for (int n = 0; n < 8; n++)
            #pragma unroll
            for (int r = 0; r < 4; r++) acc[m][n][r] = 0.f;

    // cp.async staging map
    const int sr0 = tid >> 2,         sg0 = tid & 3;
    const int sr1 = (tid + 256) >> 2, sg1 = tid & 3;
    const uint32_t smU = s2u(sm);
    const size_t gA = (size_t)rowA * D, gB = (size_t)rowB * D;

    #define STAGE(buf, c) do {                                                         \
        const uint32_t bo = (buf) * (BM * RSTR * 2);                                   \
        const size_t ko = (size_t)(c) * KCH;                                           \
        CP_ASYNC16(smU + OFF_AHI + bo + (sr0 * RSTR + sg0 * 8) * 2, g_hi + gA + sr0 * D + ko + sg0 * 8); \
        CP_ASYNC16(smU + OFF_AHI + bo + (sr1 * RSTR + sg1 * 8) * 2, g_hi + gA + sr1 * D + ko + sg1 * 8); \
        CP_ASYNC16(smU + OFF_ALO + bo + (sr0 * RSTR + sg0 * 8) * 2, g_lo + gA + sr0 * D + ko + sg0 * 8); \
        CP_ASYNC16(smU + OFF_ALO + bo + (sr1 * RSTR + sg1 * 8) * 2, g_lo + gA + sr1 * D + ko + sg1 * 8); \
        CP_ASYNC16(smU + OFF_BHI + bo + (sr0 * RSTR + sg0 * 8) * 2, g_hi + gB + sr0 * D + ko + sg0 * 8); \
        CP_ASYNC16(smU + OFF_BHI + bo + (sr1 * RSTR + sg1 * 8) * 2, g_hi + gB + sr1 * D + ko + sg1 * 8); \
        CP_ASYNC16(smU + OFF_BLO + bo + (sr0 * RSTR + sg0 * 8) * 2, g_lo + gB + sr0 * D + ko + sg0 * 8); \
        CP_ASYNC16(smU + OFF_BLO + bo + (sr1 * RSTR + sg1 * 8) * 2, g_lo + gB + sr1 * D + ko + sg1 * 8); \
        CP_COMMIT();                                                                   \
    } while (0)

    // ldmatrix lane address offsets (bytes, relative to array+buffer base)
    const uint32_t aoff = (((uint32_t)(wm * 32 + (lane & 15))) * RSTR + (lane >> 4) * 8) * 2;
    const uint32_t boff = (((uint32_t)(wn * 64 + (lane & 7) + ((lane >> 4) * 8))) * RSTR
                          + ((lane >> 3) & 1) * 8) * 2;

    STAGE(0, 0);

    for (int c = 0; c < NCH; c++) {
        const int buf = c & 1;
        if (c + 1 < NCH) { STAGE(buf ^ 1, c + 1); CP_WAIT1(); }
        else             { CP_WAIT0(); }
        __syncthreads();

        const uint32_t bufo = (uint32_t)buf * (BM * RSTR * 2);
        const uint32_t aHi = smU + OFF_AHI + bufo + aoff;
        const uint32_t aLo = smU + OFF_ALO + bufo + aoff;
        const uint32_t bHi = smU + OFF_BHI + bufo + boff;
        const uint32_t bLo = smU + OFF_BLO + bufo + boff;

        #pragma unroll
        for (int ks = 0; ks < 2; ks++) {
            const uint32_t kso = ks * 32;                // 16 halves
            uint32_t ahi[2][4], alo[2][4];
            LDSM4(ahi[0], aHi + kso);
            LDSM4(ahi[1], aHi + kso + 16 * RSTR * 2);
            LDSM4(alo[0], aLo + kso);
            LDSM4(alo[1], aLo + kso + 16 * RSTR * 2);
            #pragma unroll
            for (int nb = 0; nb < 4; nb++) {
                const uint32_t nbo = kso + nb * 16 * RSTR * 2;
                uint32_t bh[4], bl[4];
                LDSM4(bh, bHi + nbo);
                LDSM4(bl, bLo + nbo);
                const int n0 = 2 * nb, n1 = 2 * nb + 1;
                mma_f16(acc[0][n0], ahi[0], bh[0], bh[1]);
                mma_f16(acc[1][n0], ahi[1], bh[0], bh[1]);
                mma_f16(acc[0][n1], ahi[0], bh[2], bh[3]);
                mma_f16(acc[1][n1], ahi[1], bh[2], bh[3]);
                mma_f16(acc[0][n0], alo[0], bh[0], bh[1]);
                mma_f16(acc[1][n0], alo[1], bh[0], bh[1]);
                mma_f16(acc[0][n1], alo[0], bh[2], bh[3]);
                mma_f16(acc[1][n1], alo[1], bh[2], bh[3]);
                mma_f16(acc[0][n0], ahi[0], bl[0], bl[1]);
                mma_f16(acc[1][n0], ahi[1], bl[0], bl[1]);
                mma_f16(acc[0][n1], ahi[0], bl[2], bl[3]);
                mma_f16(acc[1][n1], ahi[1], bl[2], bl[3]);
            }
        }
        __syncthreads();
    }

    // -------- epilogue: l2 -> 5-kernel sum -> rank-12 weight (fp32) --------
    const float coef = g_coef;
    float lsum = 0.f;
    #pragma unroll
    for (int m = 0; m < 2; m++) {
        #pragma unroll
        for (int h = 0; h < 2; h++) {
            const int i = rowA + wm * 32 + m * 16 + gq + 8 * h;
            const float sqi = g_sq[i];
            float zi[C];
            #pragma unroll
            for (int cc = 0; cc < C; cc++) zi[cc] = g_z[(size_t)i * C + cc];
            #pragma unroll
            for (int n = 0; n < 8; n++) {
                #pragma unroll
                for (int p = 0; p < 2; p++) {
                    const int j = wn * 64 + n * 8 + 2 * gr + p;
                    const float gv = acc[m][n][2 * h + p];
                    float l2 = fmaxf(fmaf(-2.f, gv, sqi + sqB[j]), 0.f);
                    float e;
                    asm("ex2.approx.ftz.f32 %0, %1;" : "=f"(e) : "f"(l2 * coef));
                    float e2 = e * e, e4 = e2 * e2, e8 = e4 * e4, e16 = e8 * e8;
                    float ks5 = e + e2 + e4 + e8 + e16;
                    float w = 0.f;
                    #pragma unroll
                    for (int cc = 0; cc < C; cc++) w = fmaf(zi[cc], zB[j * C + cc], w);
                    lsum = fmaf(w, ks5, lsum);
                }
            }
        }
    }
    if (bi != bj) lsum *= 2.f;

    #pragma unroll
    for (int o = 16; o > 0; o >>= 1) lsum += __shfl_xor_sync(0xffffffffu, lsum, o);
    if (lane == 0) red[wid] = lsum;
    __syncthreads();
    if (tid == 0) {
        float s = 0.f;
        #pragma unroll
        for (int w = 0; w < 8; w++) s += red[w];
        atomicAdd(&g_loss, (double)s);
    }
}

// ================================================ launch 4: output
__global__ void k_out(float* out) {
    float f = (float)(g_loss / 12.0);
    if (!isfinite(f)) f = 0.f;
    out[0] = f;
}

// ================================================================ launch
extern "C" void kernel_launch(void* const* d_in, const int* in_sizes, int n_in,
                              void* d_out, int out_size) {
    const float* src = (const float*)d_in[0];
    const float* tgt = (const float*)d_in[1];
    const float* sl  = (const float*)d_in[2];
    const float* tl  = (const float*)d_in[3];
    float* out = (float*)d_out;

    cudaFuncSetAttribute(k_mmd, cudaFuncAttributeMaxDynamicSharedMemorySize, SMEM_REQ);

    k_split<<<(NROWS * D / 4) / 256, 256>>>(src, tgt);   // launch 0
    k_stats<<<1, 256>>>(sl, tl);                         // launch 1
    k_prep<<<128, 256>>>(src, tgt, sl, tl);              // launch 2
    k_mmd<<<NTILES, 256, SMEM_REQ>>>();                  // launch 3  (profiled)
    k_out<<<1, 1>>>(out);                                // launch 4
}

// round 6
// speedup vs baseline: 3.0845x; 1.7603x over previous
#include <cuda_runtime.h>
#include <cuda_fp16.h>
#include <math.h>
#include <stdint.h>

#define NROWS 4096
#define BHALF 2048
#define D     1024
#define C     12
#define BM    128
#define NT    (NROWS / BM)          // 32
#define NTILES (NT * (NT + 1) / 2)  // 528
#define KCH   32
#define NCH   (D / KCH)             // 32
#define RSTR  40                    // smem row stride in halves (32 + 8 pad)

#define ARR_BYTES (2 * BM * RSTR * 2)
#define OFF_AHI 0
#define OFF_ALO (1 * ARR_BYTES)
#define OFF_BHI (2 * ARR_BYTES)
#define OFF_BLO (3 * ARR_BYTES)
#define OFF_ZB  (4 * ARR_BYTES)
#define OFF_SQB (OFF_ZB + BM * C * 4)
#define SMEM_REQ (OFF_SQB + BM * 4 + 256)

// ---- scratch (device globals; no allocation allowed) ----
__device__ __half g_hi[(size_t)NROWS * D];
__device__ __half g_lo[(size_t)NROWS * D];
__device__ float  g_z[NROWS * C];
__device__ float  g_sq[NROWS];
__device__ float  g_colsum[D];
__device__ float  g_cpart[16][C];     // per-block class-sum partials
__device__ int    g_prespart[16];     // per-block presence bitmasks
__device__ double g_loss;
__device__ float  g_coef;

static __device__ __forceinline__ uint32_t s2u(const void* p) {
    uint32_t a;
    asm("{ .reg .u64 t; cvta.to.shared.u64 t, %1; cvt.u32.u64 %0, t; }" : "=r"(a) : "l"(p));
    return a;
}

#define CP_ASYNC16(dst, src) \
    asm volatile("cp.async.cg.shared.global [%0], [%1], 16;" :: "r"(dst), "l"(src))
#define CP_COMMIT()  asm volatile("cp.async.commit_group;" ::: "memory")
#define CP_WAIT1()   asm volatile("cp.async.wait_group 1;" ::: "memory")
#define CP_WAIT0()   asm volatile("cp.async.wait_group 0;" ::: "memory")

#define LDSM4(r, a) \
    asm volatile("ldmatrix.sync.aligned.m8n8.x4.shared.b16 {%0,%1,%2,%3}, [%4];" \
        : "=r"((r)[0]), "=r"((r)[1]), "=r"((r)[2]), "=r"((r)[3]) : "r"(a))

static __device__ __forceinline__ void mma_f16(float* c, const uint32_t* a,
                                               uint32_t b0, uint32_t b1) {
    asm volatile(
        "mma.sync.aligned.m16n8k16.row.col.f32.f16.f16.f32 "
        "{%0,%1,%2,%3}, {%4,%5,%6,%7}, {%8,%9}, {%0,%1,%2,%3};"
        : "+f"(c[0]), "+f"(c[1]), "+f"(c[2]), "+f"(c[3])
        : "r"(a[0]), "r"(a[1]), "r"(a[2]), "r"(a[3]), "r"(b0), "r"(b1));
}

// ============== launch 0: per-block class sums + presence; zero colsum
__global__ void k_labels(const float* __restrict__ sl, const float* __restrict__ tl) {
    __shared__ float cs[C];
    __shared__ int   pres;
    const int tid = threadIdx.x, b = blockIdx.x;
    if (tid < C) cs[tid] = 0.f;
    if (tid == 0) pres = 0;
    // zero colsum slab (this launch precedes k_main)
    if (tid < 64) g_colsum[b * 64 + tid] = 0.f;
    __syncthreads();

    const int row = b * 256 + tid;                 // 0..4095, one row per thread
    const float* p = (row < BHALF) ? (sl + (size_t)row * C)
                                   : (tl + (size_t)(row - BHALF) * C);
    float best = -INFINITY; int arg = 0;
    #pragma unroll
    for (int c = 0; c < C; c++) {
        float v = p[c];
        atomicAdd(&cs[c], v);
        if (v > best) { best = v; arg = c; }       // first max == jnp.argmax
    }
    atomicOr(&pres, 1 << arg);
    __syncthreads();
    if (tid < C) g_cpart[b][tid] = cs[tid];
    if (tid == 0) g_prespart[b] = pres;
}

// ============== launch 1: fused split(hi/lo) + row-sq + colsum (one 16MB pass)
__global__ void k_main(const float* __restrict__ src, const float* __restrict__ tgt) {
    __shared__ float scol[D];
    const int tid = threadIdx.x, lane = tid & 31, w = tid >> 5;
    const int r0 = blockIdx.x * 32;
    const float* base = (r0 < BHALF) ? src + (size_t)r0 * D : tgt + (size_t)(r0 - BHALF) * D;

    for (int c = tid; c < D; c += 256) scol[c] = 0.f;
    __syncthreads();

    float4 csum[8];
    #pragma unroll
    for (int j = 0; j < 8; j++) csum[j] = make_float4(0.f, 0.f, 0.f, 0.f);

    #pragma unroll
    for (int t = 0; t < 4; t++) {
        const int rr = w + 8 * t;
        const float* p = base + (size_t)rr * D;
        __half* ph = g_hi + (size_t)(r0 + rr) * D;
        __half* pl = g_lo + (size_t)(r0 + rr) * D;
        float sq = 0.f;
        #pragma unroll
        for (int j = 0; j < 8; j++) {
            const int col = lane * 4 + 128 * j;
            float4 v = *(const float4*)(p + col);
            sq += v.x * v.x + v.y * v.y + v.z * v.z + v.w * v.w;
            csum[j].x += v.x; csum[j].y += v.y; csum[j].z += v.z; csum[j].w += v.w;
            __half h[4], l[4];
            float vv[4] = {v.x, v.y, v.z, v.w};
            #pragma unroll
            for (int q = 0; q < 4; q++) {
                h[q] = __float2half_rn(vv[q]);
                l[q] = __float2half_rn(vv[q] - __half2float(h[q]));
            }
            *(uint2*)(ph + col) = *(uint2*)h;
            *(uint2*)(pl + col) = *(uint2*)l;
        }
        #pragma unroll
        for (int o = 16; o > 0; o >>= 1) sq += __shfl_xor_sync(0xffffffffu, sq, o);
        if (lane == 0) g_sq[r0 + rr] = sq;
    }
    // block-level column sums
    #pragma unroll
    for (int j = 0; j < 8; j++) {
        const int col = lane * 4 + 128 * j;
        atomicAdd(&scol[col + 0], csum[j].x);
        atomicAdd(&scol[col + 1], csum[j].y);
        atomicAdd(&scol[col + 2], csum[j].z);
        atomicAdd(&scol[col + 3], csum[j].w);
    }
    __syncthreads();
    #pragma unroll
    for (int q = 0; q < 4; q++) {
        const int c = tid + 256 * q;
        atomicAdd(&g_colsum[c], scol[c]);
    }
}

// ============== launch 2: factors + z + sumsq + colsq + bandwidth
__global__ void k_fin(const float* __restrict__ sl, const float* __restrict__ tl) {
    __shared__ float sfac[C], tfac[C];
    __shared__ double dr[256];
    const int tid = threadIdx.x;

    if (tid < C) {
        float ss = 0.f, ts = 0.f;
        int sp = 0, tp = 0;
        #pragma unroll
        for (int b = 0; b < 8; b++)  { ss += g_cpart[b][tid];     sp |= g_prespart[b]; }
        #pragma unroll
        for (int b = 8; b < 16; b++) { ts += g_cpart[b][tid];     tp |= g_prespart[b]; }
        bool common = ((sp >> tid) & 1) && ((tp >> tid) & 1);
        sfac[tid] = (common && ss > 0.f) ?  1.f / ss : 0.f;
        tfac[tid] = (common && ts > 0.f) ? -1.f / ts : 0.f;
    }
    __syncthreads();
    // z vectors
    for (int idx = tid; idx < NROWS * C; idx += 256) {
        int r = idx / C, c = idx - r * C;
        float v = (r < BHALF) ? sl[(size_t)r * C + c] * sfac[c]
                              : tl[(size_t)(r - BHALF) * C + c] * tfac[c];
        g_z[idx] = v;
    }
    // sum of row-squares
    double s = 0.0;
    for (int i = tid; i < NROWS; i += 256) s += (double)g_sq[i];
    dr[tid] = s;
    __syncthreads();
    for (int o = 128; o > 0; o >>= 1) {
        if (tid < o) dr[tid] += dr[tid + o];
        __syncthreads();
    }
    double sumsq = dr[0];
    __syncthreads();
    // ||colsum||^2
    s = 0.0;
    for (int c = tid; c < D; c += 256) { double v = (double)g_colsum[c]; s += v * v; }
    dr[tid] = s;
    __syncthreads();
    for (int o = 128; o > 0; o >>= 1) {
        if (tid < o) dr[tid] += dr[tid + o];
        __syncthreads();
    }
    if (tid == 0) {
        const double n = (double)NROWS;
        double sum_l2 = 2.0 * n * sumsq - 2.0 * dr[0];
        double bw = sum_l2 / (n * n - n) / 4.0;
        g_coef = (float)(-1.0 / (16.0 * bw * 0.6931471805599453));
        g_loss = 0.0;
    }
}

// ============== launch 3 (profiled): fp16-split mma.sync fused GEMM + MMD
__global__ __launch_bounds__(256, 2) void k_mmd() {
    extern __shared__ __align__(16) unsigned char sm[];
    float* zB  = (float*)(sm + OFF_ZB);
    float* sqB = (float*)(sm + OFF_SQB);
    __shared__ float red[8];

    const int tid = threadIdx.x, wid = tid >> 5, lane = tid & 31;
    const int wm = wid >> 1, wn = wid & 1;
    const int gq = lane >> 2, gr = lane & 3;

    int L = blockIdx.x, bi = 0;
    while (L >= NT - bi) { L -= NT - bi; bi++; }
    int bj = bi + L;
    const int rowA = bi * BM, rowB = bj * BM;

    for (int t = tid; t < BM * C; t += 256)
        zB[t] = g_z[(size_t)(rowB + t / C) * C + (t % C)];
    if (tid < BM) sqB[tid] = g_sq[rowB + tid];

    float acc[2][8][4];
    #pragma unroll
    for (int m = 0; m < 2; m++)
        #pragma unroll
        for (int n = 0; n < 8; n++)
            #pragma unroll
            for (int r = 0; r < 4; r++) acc[m][n][r] = 0.f;

    const int sr0 = tid >> 2,         sg0 = tid & 3;
    const int sr1 = (tid + 256) >> 2, sg1 = tid & 3;
    const uint32_t smU = s2u(sm);
    const size_t gA = (size_t)rowA * D, gB = (size_t)rowB * D;

    #define STAGE(buf, c) do {                                                         \
        const uint32_t bo = (buf) * (BM * RSTR * 2);                                   \
        const size_t ko = (size_t)(c) * KCH;                                           \
        CP_ASYNC16(smU + OFF_AHI + bo + (sr0 * RSTR + sg0 * 8) * 2, g_hi + gA + sr0 * D + ko + sg0 * 8); \
        CP_ASYNC16(smU + OFF_AHI + bo + (sr1 * RSTR + sg1 * 8) * 2, g_hi + gA + sr1 * D + ko + sg1 * 8); \
        CP_ASYNC16(smU + OFF_ALO + bo + (sr0 * RSTR + sg0 * 8) * 2, g_lo + gA + sr0 * D + ko + sg0 * 8); \
        CP_ASYNC16(smU + OFF_ALO + bo + (sr1 * RSTR + sg1 * 8) * 2, g_lo + gA + sr1 * D + ko + sg1 * 8); \
        CP_ASYNC16(smU + OFF_BHI + bo + (sr0 * RSTR + sg0 * 8) * 2, g_hi + gB + sr0 * D + ko + sg0 * 8); \
        CP_ASYNC16(smU + OFF_BHI + bo + (sr1 * RSTR + sg1 * 8) * 2, g_hi + gB + sr1 * D + ko + sg1 * 8); \
        CP_ASYNC16(smU + OFF_BLO + bo + (sr0 * RSTR + sg0 * 8) * 2, g_lo + gB + sr0 * D + ko + sg0 * 8); \
        CP_ASYNC16(smU + OFF_BLO + bo + (sr1 * RSTR + sg1 * 8) * 2, g_lo + gB + sr1 * D + ko + sg1 * 8); \
        CP_COMMIT();                                                                   \
    } while (0)

    const uint32_t aoff = (((uint32_t)(wm * 32 + (lane & 15))) * RSTR + (lane >> 4) * 8) * 2;
    const uint32_t boff = (((uint32_t)(wn * 64 + (lane & 7) + ((lane >> 4) * 8))) * RSTR
                          + ((lane >> 3) & 1) * 8) * 2;

    STAGE(0, 0);

    for (int c = 0; c < NCH; c++) {
        const int buf = c & 1;
        if (c + 1 < NCH) { STAGE(buf ^ 1, c + 1); CP_WAIT1(); }
        else             { CP_WAIT0(); }
        __syncthreads();

        const uint32_t bufo = (uint32_t)buf * (BM * RSTR * 2);
        const uint32_t aHi = smU + OFF_AHI + bufo + aoff;
        const uint32_t aLo = smU + OFF_ALO + bufo + aoff;
        const uint32_t bHi = smU + OFF_BHI + bufo + boff;
        const uint32_t bLo = smU + OFF_BLO + bufo + boff;

        #pragma unroll
        for (int ks = 0; ks < 2; ks++) {
            const uint32_t kso = ks * 32;
            uint32_t ahi[2][4], alo[2][4];
            LDSM4(ahi[0], aHi + kso);
            LDSM4(ahi[1], aHi + kso + 16 * RSTR * 2);
            LDSM4(alo[0], aLo + kso);
            LDSM4(alo[1], aLo + kso + 16 * RSTR * 2);
            #pragma unroll
            for (int nb = 0; nb < 4; nb++) {
                const uint32_t nbo = kso + nb * 16 * RSTR * 2;
                uint32_t bh[4], bl[4];
                LDSM4(bh, bHi + nbo);
                LDSM4(bl, bLo + nbo);
                const int n0 = 2 * nb, n1 = 2 * nb + 1;
                mma_f16(acc[0][n0], ahi[0], bh[0], bh[1]);
                mma_f16(acc[1][n0], ahi[1], bh[0], bh[1]);
                mma_f16(acc[0][n1], ahi[0], bh[2], bh[3]);
                mma_f16(acc[1][n1], ahi[1], bh[2], bh[3]);
                mma_f16(acc[0][n0], alo[0], bh[0], bh[1]);
                mma_f16(acc[1][n0], alo[1], bh[0], bh[1]);
                mma_f16(acc[0][n1], alo[0], bh[2], bh[3]);
                mma_f16(acc[1][n1], alo[1], bh[2], bh[3]);
                mma_f16(acc[0][n0], ahi[0], bl[0], bl[1]);
                mma_f16(acc[1][n0], ahi[1], bl[0], bl[1]);
                mma_f16(acc[0][n1], ahi[0], bl[2], bl[3]);
                mma_f16(acc[1][n1], ahi[1], bl[2], bl[3]);
            }
        }
        __syncthreads();
    }

    const float coef = g_coef;
    float lsum = 0.f;
    #pragma unroll
    for (int m = 0; m < 2; m++) {
        #pragma unroll
        for (int h = 0; h < 2; h++) {
            const int i = rowA + wm * 32 + m * 16 + gq + 8 * h;
            const float sqi = g_sq[i];
            float zi[C];
            #pragma unroll
            for (int cc = 0; cc < C; cc++) zi[cc] = g_z[(size_t)i * C + cc];
            #pragma unroll
            for (int n = 0; n < 8; n++) {
                #pragma unroll
                for (int p = 0; p < 2; p++) {
                    const int j = wn * 64 + n * 8 + 2 * gr + p;
                    const float gv = acc[m][n][2 * h + p];
                    float l2 = fmaxf(fmaf(-2.f, gv, sqi + sqB[j]), 0.f);
                    float e;
                    asm("ex2.approx.ftz.f32 %0, %1;" : "=f"(e) : "f"(l2 * coef));
                    float e2 = e * e, e4 = e2 * e2, e8 = e4 * e4, e16 = e8 * e8;
                    float ks5 = e + e2 + e4 + e8 + e16;
                    float w = 0.f;
                    #pragma unroll
                    for (int cc = 0; cc < C; cc++) w = fmaf(zi[cc], zB[j * C + cc], w);
                    lsum = fmaf(w, ks5, lsum);
                }
            }
        }
    }
    if (bi != bj) lsum *= 2.f;

    #pragma unroll
    for (int o = 16; o > 0; o >>= 1) lsum += __shfl_xor_sync(0xffffffffu, lsum, o);
    if (lane == 0) red[wid] = lsum;
    __syncthreads();
    if (tid == 0) {
        float s = 0.f;
        #pragma unroll
        for (int w = 0; w < 8; w++) s += red[w];
        atomicAdd(&g_loss, (double)s);
    }
}

// ============== launch 4: output
__global__ void k_out(float* out) {
    float f = (float)(g_loss / 12.0);
    if (!isfinite(f)) f = 0.f;
    out[0] = f;
}

// ================================================================ launch
extern "C" void kernel_launch(void* const* d_in, const int* in_sizes, int n_in,
                              void* d_out, int out_size) {
    const float* src = (const float*)d_in[0];
    const float* tgt = (const float*)d_in[1];
    const float* sl  = (const float*)d_in[2];
    const float* tl  = (const float*)d_in[3];
    float* out = (float*)d_out;

    cudaFuncSetAttribute(k_mmd, cudaFuncAttributeMaxDynamicSharedMemorySize, SMEM_REQ);

    k_labels<<<16, 256>>>(sl, tl);        // launch 0
    k_main<<<128, 256>>>(src, tgt);       // launch 1
    k_fin<<<1, 256>>>(sl, tl);            // launch 2
    k_mmd<<<NTILES, 256, SMEM_REQ>>>();   // launch 3 (profiled)
    k_out<<<1, 1>>>(out);                 // launch 4
}

// round 7
// speedup vs baseline: 3.6279x; 1.1762x over previous
#include <cuda_runtime.h>
#include <cuda_fp16.h>
#include <math.h>
#include <stdint.h>

#define NROWS 4096
#define BHALF 2048
#define D     1024
#define C     12
#define BM    128
#define NT    (NROWS / BM)          // 32
#define NTILES (NT * (NT + 1) / 2)  // 528
#define KCH   32
#define NCH   (D / KCH)             // 32
#define RSTR  40                    // smem row stride in halves (32 + 8 pad)

#define ARR_BYTES (2 * BM * RSTR * 2)
#define OFF_AHI 0
#define OFF_ALO (1 * ARR_BYTES)
#define OFF_BHI (2 * ARR_BYTES)
#define OFF_BLO (3 * ARR_BYTES)
#define OFF_ZB  (4 * ARR_BYTES)
#define OFF_SQB (OFF_ZB + BM * C * 4)
#define SMEM_REQ (OFF_SQB + BM * 4 + 256)

// ---- scratch (device globals; no allocation allowed) ----
__device__ __half g_hi[(size_t)NROWS * D];
__device__ __half g_lo[(size_t)NROWS * D];
__device__ float  g_z[NROWS * C];
__device__ float  g_sq[NROWS];
__device__ float  g_colsum[D];
__device__ float  g_cpart[16][C];
__device__ int    g_prespart[16];
__device__ double g_loss;
__device__ float  g_coef;

static __device__ __forceinline__ uint32_t s2u(const void* p) {
    uint32_t a;
    asm("{ .reg .u64 t; cvta.to.shared.u64 t, %1; cvt.u32.u64 %0, t; }" : "=r"(a) : "l"(p));
    return a;
}

#define CP_ASYNC16(dst, src) \
    asm volatile("cp.async.cg.shared.global [%0], [%1], 16;" :: "r"(dst), "l"(src))
#define CP_COMMIT()  asm volatile("cp.async.commit_group;" ::: "memory")
#define CP_WAIT1()   asm volatile("cp.async.wait_group 1;" ::: "memory")
#define CP_WAIT0()   asm volatile("cp.async.wait_group 0;" ::: "memory")

#define LDSM4(r, a) \
    asm volatile("ldmatrix.sync.aligned.m8n8.x4.shared.b16 {%0,%1,%2,%3}, [%4];" \
        : "=r"((r)[0]), "=r"((r)[1]), "=r"((r)[2]), "=r"((r)[3]) : "r"(a))

static __device__ __forceinline__ void mma_f16(float* c, const uint32_t* a,
                                               uint32_t b0, uint32_t b1) {
    asm volatile(
        "mma.sync.aligned.m16n8k16.row.col.f32.f16.f16.f32 "
        "{%0,%1,%2,%3}, {%4,%5,%6,%7}, {%8,%9}, {%0,%1,%2,%3};"
        : "+f"(c[0]), "+f"(c[1]), "+f"(c[2]), "+f"(c[3])
        : "r"(a[0]), "r"(a[1]), "r"(a[2]), "r"(a[3]), "r"(b0), "r"(b1));
}

// ============== launch 0: class sums + presence (warp-reduced) + zero colsum
__global__ void k_labels(const float* __restrict__ sl, const float* __restrict__ tl) {
    __shared__ float cs[C];
    __shared__ int   pr;
    const int tid = threadIdx.x, lane = tid & 31, b = blockIdx.x;
    if (tid < C) cs[tid] = 0.f;
    if (tid == 0) pr = 0;
    if (tid < 64) g_colsum[b * 64 + tid] = 0.f;
    __syncthreads();

    const int row = b * 256 + tid;
    const float* p = (row < BHALF) ? (sl + (size_t)row * C)
                                   : (tl + (size_t)(row - BHALF) * C);
    float v[C];
    float4 q0 = *(const float4*)p;
    float4 q1 = *(const float4*)(p + 4);
    float4 q2 = *(const float4*)(p + 8);
    v[0] = q0.x; v[1] = q0.y; v[2]  = q0.z; v[3]  = q0.w;
    v[4] = q1.x; v[5] = q1.y; v[6]  = q1.z; v[7]  = q1.w;
    v[8] = q2.x; v[9] = q2.y; v[10] = q2.z; v[11] = q2.w;

    int arg = 0; float best = v[0];
    #pragma unroll
    for (int c = 1; c < C; c++) if (v[c] > best) { best = v[c]; arg = c; }
    unsigned pres = __reduce_or_sync(0xffffffffu, 1u << arg);

    #pragma unroll
    for (int c = 0; c < C; c++) {
        #pragma unroll
        for (int o = 16; o > 0; o >>= 1)
            v[c] += __shfl_xor_sync(0xffffffffu, v[c], o);
    }
    if (lane == 0) {
        #pragma unroll
        for (int c = 0; c < C; c++) atomicAdd(&cs[c], v[c]);
        atomicOr(&pr, (int)pres);
    }
    __syncthreads();
    if (tid < C) g_cpart[b][tid] = cs[tid];
    if (tid == 0) g_prespart[b] = pr;
}

// ============== launch 1: fused split(hi/lo) + row-sq + colsum
__global__ void k_main(const float* __restrict__ src, const float* __restrict__ tgt) {
    __shared__ float scol[D];
    const int tid = threadIdx.x, lane = tid & 31, w = tid >> 5;
    const int r0 = blockIdx.x * 32;
    const float* base = (r0 < BHALF) ? src + (size_t)r0 * D : tgt + (size_t)(r0 - BHALF) * D;

    for (int c = tid; c < D; c += 256) scol[c] = 0.f;
    __syncthreads();

    float4 csum[8];
    #pragma unroll
    for (int j = 0; j < 8; j++) csum[j] = make_float4(0.f, 0.f, 0.f, 0.f);

    #pragma unroll
    for (int t = 0; t < 4; t++) {
        const int rr = w + 8 * t;
        const float* p = base + (size_t)rr * D;
        __half* ph = g_hi + (size_t)(r0 + rr) * D;
        __half* pl = g_lo + (size_t)(r0 + rr) * D;
        float sq = 0.f;
        #pragma unroll
        for (int j = 0; j < 8; j++) {
            const int col = lane * 4 + 128 * j;
            float4 v = *(const float4*)(p + col);
            sq += v.x * v.x + v.y * v.y + v.z * v.z + v.w * v.w;
            csum[j].x += v.x; csum[j].y += v.y; csum[j].z += v.z; csum[j].w += v.w;
            __half h[4], l[4];
            float vv[4] = {v.x, v.y, v.z, v.w};
            #pragma unroll
            for (int q = 0; q < 4; q++) {
                h[q] = __float2half_rn(vv[q]);
                l[q] = __float2half_rn(vv[q] - __half2float(h[q]));
            }
            *(uint2*)(ph + col) = *(uint2*)h;
            *(uint2*)(pl + col) = *(uint2*)l;
        }
        #pragma unroll
        for (int o = 16; o > 0; o >>= 1) sq += __shfl_xor_sync(0xffffffffu, sq, o);
        if (lane == 0) g_sq[r0 + rr] = sq;
    }
    #pragma unroll
    for (int j = 0; j < 8; j++) {
        const int col = lane * 4 + 128 * j;
        atomicAdd(&scol[col + 0], csum[j].x);
        atomicAdd(&scol[col + 1], csum[j].y);
        atomicAdd(&scol[col + 2], csum[j].z);
        atomicAdd(&scol[col + 3], csum[j].w);
    }
    __syncthreads();
    #pragma unroll
    for (int q = 0; q < 4; q++) {
        const int c = tid + 256 * q;
        atomicAdd(&g_colsum[c], scol[c]);
    }
}

// ============== launch 2: factors + z + sumsq + colsq + bandwidth
__global__ void k_fin(const float* __restrict__ sl, const float* __restrict__ tl) {
    __shared__ float sfac[C], tfac[C];
    __shared__ double dr[256];
    const int tid = threadIdx.x;

    if (tid < C) {
        float ss = 0.f, ts = 0.f;
        int sp = 0, tp = 0;
        #pragma unroll
        for (int b = 0; b < 8; b++)  { ss += g_cpart[b][tid]; sp |= g_prespart[b]; }
        #pragma unroll
        for (int b = 8; b < 16; b++) { ts += g_cpart[b][tid]; tp |= g_prespart[b]; }
        bool common = ((sp >> tid) & 1) && ((tp >> tid) & 1);
        sfac[tid] = (common && ss > 0.f) ?  1.f / ss : 0.f;
        tfac[tid] = (common && ts > 0.f) ? -1.f / ts : 0.f;
    }
    __syncthreads();
    for (int idx = tid; idx < NROWS * C; idx += 256) {
        int r = idx / C, c = idx - r * C;
        float v = (r < BHALF) ? sl[(size_t)r * C + c] * sfac[c]
                              : tl[(size_t)(r - BHALF) * C + c] * tfac[c];
        g_z[idx] = v;
    }
    double s = 0.0;
    for (int i = tid; i < NROWS; i += 256) s += (double)g_sq[i];
    dr[tid] = s;
    __syncthreads();
    for (int o = 128; o > 0; o >>= 1) {
        if (tid < o) dr[tid] += dr[tid + o];
        __syncthreads();
    }
    double sumsq = dr[0];
    __syncthreads();
    s = 0.0;
    for (int c = tid; c < D; c += 256) { double v = (double)g_colsum[c]; s += v * v; }
    dr[tid] = s;
    __syncthreads();
    for (int o = 128; o > 0; o >>= 1) {
        if (tid < o) dr[tid] += dr[tid + o];
        __syncthreads();
    }
    if (tid == 0) {
        const double n = (double)NROWS;
        double sum_l2 = 2.0 * n * sumsq - 2.0 * dr[0];
        double bw = sum_l2 / (n * n - n) / 4.0;
        g_coef = (float)(-1.0 / (16.0 * bw * 0.6931471805599453));
        g_loss = 0.0;
    }
}

// ============== launch 3 (profiled): fp16-split mma.sync fused GEMM + MMD
__global__ __launch_bounds__(256, 2) void k_mmd() {
    extern __shared__ __align__(16) unsigned char sm[];
    float* zB  = (float*)(sm + OFF_ZB);
    float* sqB = (float*)(sm + OFF_SQB);
    __shared__ float red[8];

    const int tid = threadIdx.x, wid = tid >> 5, lane = tid & 31;
    const int wm = wid >> 1, wn = wid & 1;
    const int gq = lane >> 2, gr = lane & 3;

    int L = blockIdx.x, bi = 0;
    while (L >= NT - bi) { L -= NT - bi; bi++; }
    int bj = bi + L;
    const int rowA = bi * BM, rowB = bj * BM;

    for (int t = tid; t < BM * C; t += 256)
        zB[t] = g_z[(size_t)(rowB + t / C) * C + (t % C)];
    if (tid < BM) sqB[tid] = g_sq[rowB + tid];

    float acc[2][8][4];
    #pragma unroll
    for (int m = 0; m < 2; m++)
        #pragma unroll
        for (int n = 0; n < 8; n++)
            #pragma unroll
            for (int r = 0; r < 4; r++) acc[m][n][r] = 0.f;

    const int sr0 = tid >> 2,         sg0 = tid & 3;
    const int sr1 = (tid + 256) >> 2, sg1 = tid & 3;
    const uint32_t smU = s2u(sm);
    const size_t gA = (size_t)rowA * D, gB = (size_t)rowB * D;

    #define STAGE(buf, c) do {                                                         \
        const uint32_t bo = (buf) * (BM * RSTR * 2);                                   \
        const size_t ko = (size_t)(c) * KCH;                                           \
        CP_ASYNC16(smU + OFF_AHI + bo + (sr0 * RSTR + sg0 * 8) * 2, g_hi + gA + sr0 * D + ko + sg0 * 8); \
        CP_ASYNC16(smU + OFF_AHI + bo + (sr1 * RSTR + sg1 * 8) * 2, g_hi + gA + sr1 * D + ko + sg1 * 8); \
        CP_ASYNC16(smU + OFF_ALO + bo + (sr0 * RSTR + sg0 * 8) * 2, g_lo + gA + sr0 * D + ko + sg0 * 8); \
        CP_ASYNC16(smU + OFF_ALO + bo + (sr1 * RSTR + sg1 * 8) * 2, g_lo + gA + sr1 * D + ko + sg1 * 8); \
        CP_ASYNC16(smU + OFF_BHI + bo + (sr0 * RSTR + sg0 * 8) * 2, g_hi + gB + sr0 * D + ko + sg0 * 8); \
        CP_ASYNC16(smU + OFF_BHI + bo + (sr1 * RSTR + sg1 * 8) * 2, g_hi + gB + sr1 * D + ko + sg1 * 8); \
        CP_ASYNC16(smU + OFF_BLO + bo + (sr0 * RSTR + sg0 * 8) * 2, g_lo + gB + sr0 * D + ko + sg0 * 8); \
        CP_ASYNC16(smU + OFF_BLO + bo + (sr1 * RSTR + sg1 * 8) * 2, g_lo + gB + sr1 * D + ko + sg1 * 8); \
        CP_COMMIT();                                                                   \
    } while (0)

    const uint32_t aoff = (((uint32_t)(wm * 32 + (lane & 15))) * RSTR + (lane >> 4) * 8) * 2;
    const uint32_t boff = (((uint32_t)(wn * 64 + (lane & 7) + ((lane >> 4) * 8))) * RSTR
                          + ((lane >> 3) & 1) * 8) * 2;

    STAGE(0, 0);

    for (int c = 0; c < NCH; c++) {
        const int buf = c & 1;
        if (c + 1 < NCH) { STAGE(buf ^ 1, c + 1); CP_WAIT1(); }
        else             { CP_WAIT0(); }
        __syncthreads();

        const uint32_t bufo = (uint32_t)buf * (BM * RSTR * 2);
        const uint32_t aHi = smU + OFF_AHI + bufo + aoff;
        const uint32_t aLo = smU + OFF_ALO + bufo + aoff;
        const uint32_t bHi = smU + OFF_BHI + bufo + boff;
        const uint32_t bLo = smU + OFF_BLO + bufo + boff;

        #pragma unroll
        for (int ks = 0; ks < 2; ks++) {
            const uint32_t kso = ks * 32;
            uint32_t ahi[2][4], alo[2][4];
            LDSM4(ahi[0], aHi + kso);
            LDSM4(ahi[1], aHi + kso + 16 * RSTR * 2);
            LDSM4(alo[0], aLo + kso);
            LDSM4(alo[1], aLo + kso + 16 * RSTR * 2);
            // B fragments: double-buffered, prefetched one nb-step ahead
            uint32_t bh[2][4], bl[2][4];
            LDSM4(bh[0], bHi + kso);
            LDSM4(bl[0], bLo + kso);
            #pragma unroll
            for (int nb = 0; nb < 4; nb++) {
                const int cur = nb & 1, nxt = cur ^ 1;
                if (nb < 3) {
                    const uint32_t nbo = kso + (nb + 1) * 16 * RSTR * 2;
                    LDSM4(bh[nxt], bHi + nbo);
                    LDSM4(bl[nxt], bLo + nbo);
                }
                const int n0 = 2 * nb, n1 = 2 * nb + 1;
                mma_f16(acc[0][n0], ahi[0], bh[cur][0], bh[cur][1]);
                mma_f16(acc[1][n0], ahi[1], bh[cur][0], bh[cur][1]);
                mma_f16(acc[0][n1], ahi[0], bh[cur][2], bh[cur][3]);
                mma_f16(acc[1][n1], ahi[1], bh[cur][2], bh[cur][3]);
                mma_f16(acc[0][n0], alo[0], bh[cur][0], bh[cur][1]);
                mma_f16(acc[1][n0], alo[1], bh[cur][0], bh[cur][1]);
                mma_f16(acc[0][n1], alo[0], bh[cur][2], bh[cur][3]);
                mma_f16(acc[1][n1], alo[1], bh[cur][2], bh[cur][3]);
                mma_f16(acc[0][n0], ahi[0], bl[cur][0], bl[cur][1]);
                mma_f16(acc[1][n0], ahi[1], bl[cur][0], bl[cur][1]);
                mma_f16(acc[0][n1], ahi[0], bl[cur][2], bl[cur][3]);
                mma_f16(acc[1][n1], ahi[1], bl[cur][2], bl[cur][3]);
            }
        }
        __syncthreads();
    }

    const float coef = g_coef;
    float lsum = 0.f;
    #pragma unroll
    for (int m = 0; m < 2; m++) {
        #pragma unroll
        for (int h = 0; h < 2; h++) {
            const int i = rowA + wm * 32 + m * 16 + gq + 8 * h;
            const float sqi = g_sq[i];
            float zi[C];
            #pragma unroll
            for (int cc = 0; cc < C; cc++) zi[cc] = g_z[(size_t)i * C + cc];
            #pragma unroll
            for (int n = 0; n < 8; n++) {
                #pragma unroll
                for (int p = 0; p < 2; p++) {
                    const int j = wn * 64 + n * 8 + 2 * gr + p;
                    const float gv = acc[m][n][2 * h + p];
                    float l2 = fmaxf(fmaf(-2.f, gv, sqi + sqB[j]), 0.f);
                    float e;
                    asm("ex2.approx.ftz.f32 %0, %1;" : "=f"(e) : "f"(l2 * coef));
                    float e2 = e * e, e4 = e2 * e2, e8 = e4 * e4, e16 = e8 * e8;
                    float ks5 = e + e2 + e4 + e8 + e16;
                    float w = 0.f;
                    #pragma unroll
                    for (int cc = 0; cc < C; cc++) w = fmaf(zi[cc], zB[j * C + cc], w);
                    lsum = fmaf(w, ks5, lsum);
                }
            }
        }
    }
    if (bi != bj) lsum *= 2.f;

    #pragma unroll
    for (int o = 16; o > 0; o >>= 1) lsum += __shfl_xor_sync(0xffffffffu, lsum, o);
    if (lane == 0) red[wid] = lsum;
    __syncthreads();
    if (tid == 0) {
        float s = 0.f;
        #pragma unroll
        for (int w = 0; w < 8; w++) s += red[w];
        atomicAdd(&g_loss, (double)s);
    }
}

// ============== launch 4: output
__global__ void k_out(float* out) {
    float f = (float)(g_loss / 12.0);
    if (!isfinite(f)) f = 0.f;
    out[0] = f;
}

// ================================================================ launch
extern "C" void kernel_launch(void* const* d_in, const int* in_sizes, int n_in,
                              void* d_out, int out_size) {
    const float* src = (const float*)d_in[0];
    const float* tgt = (const float*)d_in[1];
    const float* sl  = (const float*)d_in[2];
    const float* tl  = (const float*)d_in[3];
    float* out = (float*)d_out;

    cudaFuncSetAttribute(k_mmd, cudaFuncAttributeMaxDynamicSharedMemorySize, SMEM_REQ);

    k_labels<<<16, 256>>>(sl, tl);        // launch 0
    k_main<<<128, 256>>>(src, tgt);       // launch 1
    k_fin<<<1, 256>>>(sl, tl);            // launch 2
    k_mmd<<<NTILES, 256, SMEM_REQ>>>();   // launch 3 (profiled)
    k_out<<<1, 1>>>(out);                 // launch 4
}

// round 9
// speedup vs baseline: 4.0281x; 1.1103x over previous
#include <cuda_runtime.h>
#include <cuda_fp16.h>
#include <math.h>
#include <stdint.h>

#define NROWS 4096
#define BHALF 2048
#define D     1024
#define C     12
#define BM    128
#define NT    (NROWS / BM)          // 32
#define NTILES (NT * (NT + 1) / 2)  // 528
#define NPERS 296                   // persistent CTAs (148 SMs x 2)
#define KCH   32
#define NCH   (D / KCH)             // 32
#define RSTR  40                    // smem row stride in halves

#define ARR_BYTES (2 * BM * RSTR * 2)
#define OFF_AHI 0
#define OFF_ALO (1 * ARR_BYTES)
#define OFF_BHI (2 * ARR_BYTES)
#define OFF_BLO (3 * ARR_BYTES)
#define OFF_ZB  (4 * ARR_BYTES)
#define OFF_SQB (OFF_ZB + BM * C * 4)
#define SMEM_REQ (OFF_SQB + BM * 4 + 256)

// ---- scratch ----
__device__ __half g_hi[(size_t)NROWS * D];
__device__ __half g_lo[(size_t)NROWS * D];
__device__ float  g_sq[NROWS];
__device__ float  g_colpart[128][D];     // per-block column-sum partials
__device__ float  g_cpart[128][C];
__device__ int    g_prespart[128];
__device__ float  g_fac[2 * C];          // [0..11]=sfac, [12..23]=tfac (signed)
__device__ double g_loss;
__device__ float  g_coef;
__device__ int    g_pctr;                // k_prep completion counter
__device__ int    g_tilectr;             // k_mmd work-stealing counter
__device__ int    g_donectr;             // k_mmd completion counter

static __device__ __forceinline__ uint32_t s2u(const void* p) {
    uint32_t a;
    asm("{ .reg .u64 t; cvta.to.shared.u64 t, %1; cvt.u32.u64 %0, t; }" : "=r"(a) : "l"(p));
    return a;
}

#define CP_ASYNC16(dst, src) \
    asm volatile("cp.async.cg.shared.global [%0], [%1], 16;" :: "r"(dst), "l"(src))
#define CP_COMMIT()  asm volatile("cp.async.commit_group;" ::: "memory")
#define CP_WAIT0()   asm volatile("cp.async.wait_group 0;" ::: "memory")

#define LDSM4(r, a) \
    asm volatile("ldmatrix.sync.aligned.m8n8.x4.shared.b16 {%0,%1,%2,%3}, [%4];" \
        : "=r"((r)[0]), "=r"((r)[1]), "=r"((r)[2]), "=r"((r)[3]) : "r"(a))

static __device__ __forceinline__ void mma_f16(float* c, const uint32_t* a,
                                               uint32_t b0, uint32_t b1) {
    asm volatile(
        "mma.sync.aligned.m16n8k16.row.col.f32.f16.f16.f32 "
        "{%0,%1,%2,%3}, {%4,%5,%6,%7}, {%8,%9}, {%0,%1,%2,%3};"
        : "+f"(c[0]), "+f"(c[1]), "+f"(c[2]), "+f"(c[3])
        : "r"(a[0]), "r"(a[1]), "r"(a[2]), "r"(a[3]), "r"(b0), "r"(b1));
}

// ============== launch 0: fused labels + split + row-sq + colsum + finalize
__global__ void k_prep(const float* __restrict__ src, const float* __restrict__ tgt,
                       const float* __restrict__ sl,  const float* __restrict__ tl) {
    __shared__ float scol[D];
    __shared__ double dr[256];
    __shared__ int lastf;
    const int tid = threadIdx.x, lane = tid & 31, w = tid >> 5;
    const int bid = blockIdx.x;
    const int r0 = bid * 32;
    const bool isSrc = (r0 < BHALF);
    const float* base = isSrc ? src + (size_t)r0 * D : tgt + (size_t)(r0 - BHALF) * D;

    for (int c = tid; c < D; c += 256) scol[c] = 0.f;

    // ---- labels: warp 0, one row per lane ----
    if (w == 0) {
        const float* lp = isSrc ? sl + (size_t)(r0 + lane) * C
                                : tl + (size_t)(r0 - BHALF + lane) * C;
        float v[C];
        float4 q0 = *(const float4*)lp;
        float4 q1 = *(const float4*)(lp + 4);
        float4 q2 = *(const float4*)(lp + 8);
        v[0] = q0.x; v[1] = q0.y; v[2]  = q0.z; v[3]  = q0.w;
        v[4] = q1.x; v[5] = q1.y; v[6]  = q1.z; v[7]  = q1.w;
        v[8] = q2.x; v[9] = q2.y; v[10] = q2.z; v[11] = q2.w;
        int arg = 0; float best = v[0];
        #pragma unroll
        for (int c = 1; c < C; c++) if (v[c] > best) { best = v[c]; arg = c; }
        unsigned pres = __reduce_or_sync(0xffffffffu, 1u << arg);
        #pragma unroll
        for (int c = 0; c < C; c++) {
            #pragma unroll
            for (int o = 16; o > 0; o >>= 1)
                v[c] += __shfl_xor_sync(0xffffffffu, v[c], o);
        }
        if (lane == 0) {
            #pragma unroll
            for (int c = 0; c < C; c++) g_cpart[bid][c] = v[c];
            g_prespart[bid] = (int)pres;
        }
    }
    __syncthreads();

    // ---- split hi/lo + row-sq + per-block colsum ----
    float4 csum[8];
    #pragma unroll
    for (int j = 0; j < 8; j++) csum[j] = make_float4(0.f, 0.f, 0.f, 0.f);
    #pragma unroll
    for (int t = 0; t < 4; t++) {
        const int rr = w + 8 * t;
        const float* p = base + (size_t)rr * D;
        __half* ph = g_hi + (size_t)(r0 + rr) * D;
        __half* pl = g_lo + (size_t)(r0 + rr) * D;
        float sq = 0.f;
        #pragma unroll
        for (int j = 0; j < 8; j++) {
            const int col = lane * 4 + 128 * j;
            float4 v = *(const float4*)(p + col);
            sq += v.x * v.x + v.y * v.y + v.z * v.z + v.w * v.w;
            csum[j].x += v.x; csum[j].y += v.y; csum[j].z += v.z; csum[j].w += v.w;
            __half h[4], l[4];
            float vv[4] = {v.x, v.y, v.z, v.w};
            #pragma unroll
            for (int q = 0; q < 4; q++) {
                h[q] = __float2half_rn(vv[q]);
                l[q] = __float2half_rn(vv[q] - __half2float(h[q]));
            }
            *(uint2*)(ph + col) = *(uint2*)h;
            *(uint2*)(pl + col) = *(uint2*)l;
        }
        #pragma unroll
        for (int o = 16; o > 0; o >>= 1) sq += __shfl_xor_sync(0xffffffffu, sq, o);
        if (lane == 0) g_sq[r0 + rr] = sq;
    }
    #pragma unroll
    for (int j = 0; j < 8; j++) {
        const int col = lane * 4 + 128 * j;
        atomicAdd(&scol[col + 0], csum[j].x);
        atomicAdd(&scol[col + 1], csum[j].y);
        atomicAdd(&scol[col + 2], csum[j].z);
        atomicAdd(&scol[col + 3], csum[j].w);
    }
    __syncthreads();
    #pragma unroll
    for (int q = 0; q < 4; q++) {
        const int c = tid + 256 * q;
        g_colpart[bid][c] = scol[c];
    }
    __threadfence();
    __syncthreads();
    if (tid == 0) lastf = (atomicAdd(&g_pctr, 1) == 127) ? 1 : 0;
    __syncthreads();
    if (!lastf) return;

    // ---- finalize (last block) ----
    if (tid < C) {
        float ss = 0.f, ts = 0.f;
        int sp = 0, tp = 0;
        for (int b = 0; b < 64; b++)   { ss += g_cpart[b][tid]; sp |= g_prespart[b]; }
        for (int b = 64; b < 128; b++) { ts += g_cpart[b][tid]; tp |= g_prespart[b]; }
        bool common = ((sp >> tid) & 1) && ((tp >> tid) & 1);
        g_fac[tid]     = (common && ss > 0.f) ?  1.f / ss : 0.f;
        g_fac[C + tid] = (common && ts > 0.f) ? -1.f / ts : 0.f;
    }
    double s = 0.0;
    for (int i = tid; i < NROWS; i += 256) s += (double)g_sq[i];
    dr[tid] = s;
    __syncthreads();
    for (int o = 128; o > 0; o >>= 1) {
        if (tid < o) dr[tid] += dr[tid + o];
        __syncthreads();
    }
    double sumsq = dr[0];
    __syncthreads();
    s = 0.0;
    for (int c = tid; c < D; c += 256) {
        float cs = 0.f;
        for (int b = 0; b < 128; b++) cs += g_colpart[b][c];
        s += (double)cs * (double)cs;
    }
    dr[tid] = s;
    __syncthreads();
    for (int o = 128; o > 0; o >>= 1) {
        if (tid < o) dr[tid] += dr[tid + o];
        __syncthreads();
    }
    if (tid == 0) {
        const double n = (double)NROWS;
        double sum_l2 = 2.0 * n * sumsq - 2.0 * dr[0];
        double bw = sum_l2 / (n * n - n) / 4.0;
        g_coef = (float)(-1.0 / (16.0 * bw * 0.6931471805599453));
        g_loss = 0.0;
        g_tilectr = 0;
        g_donectr = 0;
        g_pctr = 0;                       // reset for next graph replay
    }
}

// ============== launch 1: persistent fp16-split MMA + MMD + output
__global__ __launch_bounds__(256, 2) void k_mmd(const float* __restrict__ sl,
                                                const float* __restrict__ tl,
                                                float* __restrict__ out) {
    extern __shared__ __align__(16) unsigned char sm[];
    float* zB  = (float*)(sm + OFF_ZB);
    float* sqB = (float*)(sm + OFF_SQB);
    __shared__ float red[8];
    __shared__ float s_fac[2 * C];
    __shared__ int s_tile;

    const int tid = threadIdx.x, wid = tid >> 5, lane = tid & 31;
    const int wm = wid >> 1, wn = wid & 1;
    const int gq = lane >> 2, gr = lane & 3;
    const uint32_t smU = s2u(sm);

    if (tid < 2 * C) s_fac[tid] = g_fac[tid];

    const int sr0 = tid >> 2,         sg0 = tid & 3;
    const int sr1 = (tid + 256) >> 2, sg1 = tid & 3;
    const uint32_t aoff = (((uint32_t)(wm * 32 + (lane & 15))) * RSTR + (lane >> 4) * 8) * 2;
    const uint32_t boff = (((uint32_t)(wn * 64 + (lane & 7) + ((lane >> 4) * 8))) * RSTR
                          + ((lane >> 3) & 1) * 8) * 2;

    while (true) {
        if (tid == 0) s_tile = atomicAdd(&g_tilectr, 1);
        __syncthreads();
        const int T = s_tile;
        if (T >= NTILES) break;

        int L = T, bi = 0;
        while (L >= NT - bi) { L -= NT - bi; bi++; }
        const int bj = bi + L;
        const int rowA = bi * BM, rowB = bj * BM;
        const size_t gA = (size_t)rowA * D, gB = (size_t)rowB * D;

    #define STAGE(buf, c) do {                                                         \
        const uint32_t bo = (buf) * (BM * RSTR * 2);                                   \
        const size_t ko = (size_t)(c) * KCH;                                           \
        CP_ASYNC16(smU + OFF_AHI + bo + (sr0 * RSTR + sg0 * 8) * 2, g_hi + gA + sr0 * D + ko + sg0 * 8); \
        CP_ASYNC16(smU + OFF_AHI + bo + (sr1 * RSTR + sg1 * 8) * 2, g_hi + gA + sr1 * D + ko + sg1 * 8); \
        CP_ASYNC16(smU + OFF_ALO + bo + (sr0 * RSTR + sg0 * 8) * 2, g_lo + gA + sr0 * D + ko + sg0 * 8); \
        CP_ASYNC16(smU + OFF_ALO + bo + (sr1 * RSTR + sg1 * 8) * 2, g_lo + gA + sr1 * D + ko + sg1 * 8); \
        CP_ASYNC16(smU + OFF_BHI + bo + (sr0 * RSTR + sg0 * 8) * 2, g_hi + gB + sr0 * D + ko + sg0 * 8); \
        CP_ASYNC16(smU + OFF_BHI + bo + (sr1 * RSTR + sg1 * 8) * 2, g_hi + gB + sr1 * D + ko + sg1 * 8); \
        CP_ASYNC16(smU + OFF_BLO + bo + (sr0 * RSTR + sg0 * 8) * 2, g_lo + gB + sr0 * D + ko + sg0 * 8); \
        CP_ASYNC16(smU + OFF_BLO + bo + (sr1 * RSTR + sg1 * 8) * 2, g_lo + gB + sr1 * D + ko + sg1 * 8); \
        CP_COMMIT();                                                                   \
    } while (0)

        STAGE(0, 0);

        // stage z (on the fly from labels) and sq for B rows
        for (int t = tid; t < BM * C; t += 256) {
            const int r = rowB + t / C, c = t % C;
            zB[t] = (r < BHALF) ? sl[(size_t)r * C + c] * s_fac[c]
                                : tl[(size_t)(r - BHALF) * C + c] * s_fac[C + c];
        }
        if (tid < BM) sqB[tid] = g_sq[rowB + tid];

        float acc[2][8][4];
        #pragma unroll
        for (int m = 0; m < 2; m++)
            #pragma unroll
            for (int n = 0; n < 8; n++)
                #pragma unroll
                for (int r = 0; r < 4; r++) acc[m][n][r] = 0.f;

        for (int c = 0; c < NCH; c++) {
            const int buf = c & 1;
            CP_WAIT0();
            __syncthreads();
            if (c + 1 < NCH) STAGE(buf ^ 1, c + 1);

            const uint32_t bufo = (uint32_t)buf * (BM * RSTR * 2);
            const uint32_t aHi = smU + OFF_AHI + bufo + aoff;
            const uint32_t aLo = smU + OFF_ALO + bufo + aoff;
            const uint32_t bHi = smU + OFF_BHI + bufo + boff;
            const uint32_t bLo = smU + OFF_BLO + bufo + boff;

            #pragma unroll
            for (int ks = 0; ks < 2; ks++) {
                const uint32_t kso = ks * 32;
                uint32_t ahi[2][4], alo[2][4];
                LDSM4(ahi[0], aHi + kso);
                LDSM4(ahi[1], aHi + kso + 16 * RSTR * 2);
                LDSM4(alo[0], aLo + kso);
                LDSM4(alo[1], aLo + kso + 16 * RSTR * 2);
                uint32_t bh[2][4], bl[2][4];
                LDSM4(bh[0], bHi + kso);
                LDSM4(bl[0], bLo + kso);
                #pragma unroll
                for (int nb = 0; nb < 4; nb++) {
                    const int cur = nb & 1, nxt = cur ^ 1;
                    if (nb < 3) {
                        const uint32_t nbo = kso + (nb + 1) * 16 * RSTR * 2;
                        LDSM4(bh[nxt], bHi + nbo);
                        LDSM4(bl[nxt], bLo + nbo);
                    }
                    const int n0 = 2 * nb, n1 = 2 * nb + 1;
                    mma_f16(acc[0][n0], ahi[0], bh[cur][0], bh[cur][1]);
                    mma_f16(acc[1][n0], ahi[1], bh[cur][0], bh[cur][1]);
                    mma_f16(acc[0][n1], ahi[0], bh[cur][2], bh[cur][3]);
                    mma_f16(acc[1][n1], ahi[1], bh[cur][2], bh[cur][3]);
                    mma_f16(acc[0][n0], alo[0], bh[cur][0], bh[cur][1]);
                    mma_f16(acc[1][n0], alo[1], bh[cur][0], bh[cur][1]);
                    mma_f16(acc[0][n1], alo[0], bh[cur][2], bh[cur][3]);
                    mma_f16(acc[1][n1], alo[1], bh[cur][2], bh[cur][3]);
                    mma_f16(acc[0][n0], ahi[0], bl[cur][0], bl[cur][1]);
                    mma_f16(acc[1][n0], ahi[1], bl[cur][0], bl[cur][1]);
                    mma_f16(acc[0][n1], ahi[0], bl[cur][2], bl[cur][3]);
                    mma_f16(acc[1][n1], ahi[1], bl[cur][2], bl[cur][3]);
                }
            }
        }

        // ---- epilogue ----
        const float coef = g_coef;
        float lsum = 0.f;
        #pragma unroll
        for (int m = 0; m < 2; m++) {
            #pragma unroll
            for (int h = 0; h < 2; h++) {
                const int i = rowA + wm * 32 + m * 16 + gq + 8 * h;
                const float sqi = g_sq[i];
                const float* zp = (i < BHALF) ? sl + (size_t)i * C
                                              : tl + (size_t)(i - BHALF) * C;
                const int fo = (i < BHALF) ? 0 : C;
                float zi[C];
                {
                    float4 q0 = *(const float4*)zp;
                    float4 q1 = *(const float4*)(zp + 4);
                    float4 q2 = *(const float4*)(zp + 8);
                    zi[0] = q0.x * s_fac[fo + 0];  zi[1] = q0.y * s_fac[fo + 1];
                    zi[2] = q0.z * s_fac[fo + 2];  zi[3] = q0.w * s_fac[fo + 3];
                    zi[4] = q1.x * s_fac[fo + 4];  zi[5] = q1.y * s_fac[fo + 5];
                    zi[6] = q1.z * s_fac[fo + 6];  zi[7] = q1.w * s_fac[fo + 7];
                    zi[8] = q2.x * s_fac[fo + 8];  zi[9] = q2.y * s_fac[fo + 9];
                    zi[10] = q2.z * s_fac[fo + 10]; zi[11] = q2.w * s_fac[fo + 11];
                }
                #pragma unroll
                for (int n = 0; n < 8; n++) {
                    #pragma unroll
                    for (int p = 0; p < 2; p++) {
                        const int j = wn * 64 + n * 8 + 2 * gr + p;
                        const float gv = acc[m][n][2 * h + p];
                        float l2 = fmaxf(fmaf(-2.f, gv, sqi + sqB[j]), 0.f);
                        float e;
                        asm("ex2.approx.ftz.f32 %0, %1;" : "=f"(e) : "f"(l2 * coef));
                        float e2 = e * e, e4 = e2 * e2, e8 = e4 * e4, e16 = e8 * e8;
                        float ks5 = e + e2 + e4 + e8 + e16;
                        float w = 0.f;
                        #pragma unroll
                        for (int cc = 0; cc < C; cc++) w = fmaf(zi[cc], zB[j * C + cc], w);
                        lsum = fmaf(w, ks5, lsum);
                    }
                }
            }
        }
        if (bi != bj) lsum *= 2.f;

        #pragma unroll
        for (int o = 16; o > 0; o >>= 1) lsum += __shfl_xor_sync(0xffffffffu, lsum, o);
        if (lane == 0) red[wid] = lsum;
        __syncthreads();
        if (tid == 0) {
            float s = 0.f;
            #pragma unroll
            for (int w = 0; w < 8; w++) s += red[w];
            atomicAdd(&g_loss, (double)s);
        }
    }

    // ---- final CTA writes output ----
    if (tid == 0) {
        __threadfence();
        int d = atomicAdd(&g_donectr, 1);
        if (d == (int)gridDim.x - 1) {
            float f = (float)(g_loss / 12.0);
            if (!isfinite(f)) f = 0.f;
            out[0] = f;
        }
    }
}

// ================================================================ launch
extern "C" void kernel_launch(void* const* d_in, const int* in_sizes, int n_in,
                              void* d_out, int out_size) {
    const float* src = (const float*)d_in[0];
    const float* tgt = (const float*)d_in[1];
    const float* sl  = (const float*)d_in[2];
    const float* tl  = (const float*)d_in[3];
    float* out = (float*)d_out;

    cudaFuncSetAttribute(k_mmd, cudaFuncAttributeMaxDynamicSharedMemorySize, SMEM_REQ);

    k_prep<<<128, 256>>>(src, tgt, sl, tl);          // launch 0
    k_mmd<<<NPERS, 256, SMEM_REQ>>>(sl, tl, out);    // launch 1
}

// round 11
// speedup vs baseline: 4.1298x; 1.0253x over previous
#include <cuda_runtime.h>
#include <cuda_fp16.h>
#include <math.h>
#include <stdint.h>

#define NROWS 4096
#define BHALF 2048
#define D     1024
#define C     12
#define BM    128
#define BN    64
#define NT    32
#define NTILES2 (NT * (NT + 1))     // 1056 subtiles (two 128x64 per 128x128 tile)
#define NPERS 296
#define KCH   32
#define NCH   (D / KCH)             // 32
#define RSTR  40                    // fp16 row stride in halves (80B)
#define R8    48                    // int8 row stride in bytes (16B-aligned, conflict-free)
#define SCALE8 (1.0f / 524288.0f)   // 2^-4 * 2^-15

// smem layout: [buf][AHI|BHI|A8H|A8L|B8H|B8L] x2, then zB, sqB
#define SZ_AHI (BM * RSTR * 2)      // 10240
#define SZ_BHI (BN * RSTR * 2)      // 5120
#define SZ_A8  (BM * R8)            // 6144
#define SZ_B8  (BN * R8)            // 3072
#define BUFSZ  (SZ_AHI + SZ_BHI + 2 * SZ_A8 + 2 * SZ_B8)   // 33792
#define OFF_AHI 0
#define OFF_BHI (SZ_AHI)
#define OFF_A8H (SZ_AHI + SZ_BHI)
#define OFF_A8L (OFF_A8H + SZ_A8)
#define OFF_B8H (OFF_A8L + SZ_A8)
#define OFF_B8L (OFF_B8H + SZ_B8)
#define OFF_ZB  (2 * BUFSZ)
#define OFF_SQB (OFF_ZB + BN * C * 4)
#define SMEM_REQ (OFF_SQB + BN * 4 + 256)

// ---- scratch ----
__device__ __half         g_hi[(size_t)NROWS * D];
__device__ unsigned char  g_h8[(size_t)NROWS * D];
__device__ unsigned char  g_l8[(size_t)NROWS * D];
__device__ float  g_sq[NROWS];
__device__ float  g_colpart[128][D];
__device__ float  g_cpart[128][C];
__device__ int    g_prespart[128];
__device__ float  g_fac[2 * C];
__device__ double g_loss;
__device__ float  g_coef;
__device__ int    g_pctr;
__device__ int    g_tilectr;
__device__ int    g_donectr;

static __device__ __forceinline__ uint32_t s2u(const void* p) {
    uint32_t a;
    asm("{ .reg .u64 t; cvta.to.shared.u64 t, %1; cvt.u32.u64 %0, t; }" : "=r"(a) : "l"(p));
    return a;
}

#define CP_ASYNC16(dst, src) \
    asm volatile("cp.async.cg.shared.global [%0], [%1], 16;" :: "r"(dst), "l"(src))
#define CP_COMMIT()  asm volatile("cp.async.commit_group;" ::: "memory")
#define CP_WAIT0()   asm volatile("cp.async.wait_group 0;" ::: "memory")

#define LDSM4(r, a) \
    asm volatile("ldmatrix.sync.aligned.m8n8.x4.shared.b16 {%0,%1,%2,%3}, [%4];" \
        : "=r"((r)[0]), "=r"((r)[1]), "=r"((r)[2]), "=r"((r)[3]) : "r"(a))

static __device__ __forceinline__ void mma_f16(float* c, const uint32_t* a,
                                               uint32_t b0, uint32_t b1) {
    asm volatile(
        "mma.sync.aligned.m16n8k16.row.col.f32.f16.f16.f32 "
        "{%0,%1,%2,%3}, {%4,%5,%6,%7}, {%8,%9}, {%0,%1,%2,%3};"
        : "+f"(c[0]), "+f"(c[1]), "+f"(c[2]), "+f"(c[3])
        : "r"(a[0]), "r"(a[1]), "r"(a[2]), "r"(a[3]), "r"(b0), "r"(b1));
}

static __device__ __forceinline__ void mma_s8(int* c, const uint32_t* a,
                                              uint32_t b0, uint32_t b1) {
    asm volatile(
        "mma.sync.aligned.m16n8k32.row.col.s32.s8.s8.s32 "
        "{%0,%1,%2,%3}, {%4,%5,%6,%7}, {%8,%9}, {%0,%1,%2,%3};"
        : "+r"(c[0]), "+r"(c[1]), "+r"(c[2]), "+r"(c[3])
        : "r"(a[0]), "r"(a[1]), "r"(a[2]), "r"(a[3]), "r"(b0), "r"(b1));
}

static __device__ __forceinline__ int clamp127(int v) {
    return v < -127 ? -127 : (v > 127 ? 127 : v);
}

// ============== launch 0: fused labels + split/quant + row-sq + colsum + finalize
__global__ void k_prep(const float* __restrict__ src, const float* __restrict__ tgt,
                       const float* __restrict__ sl,  const float* __restrict__ tl) {
    __shared__ float scol[D];
    __shared__ double dr[256];
    __shared__ int lastf;
    const int tid = threadIdx.x, lane = tid & 31, w = tid >> 5;
    const int bid = blockIdx.x;
    const int r0 = bid * 32;
    const bool isSrc = (r0 < BHALF);
    const float* base = isSrc ? src + (size_t)r0 * D : tgt + (size_t)(r0 - BHALF) * D;

    for (int c = tid; c < D; c += 256) scol[c] = 0.f;

    if (w == 0) {
        const float* lp = isSrc ? sl + (size_t)(r0 + lane) * C
                                : tl + (size_t)(r0 - BHALF + lane) * C;
        float v[C];
        float4 q0 = *(const float4*)lp;
        float4 q1 = *(const float4*)(lp + 4);
        float4 q2 = *(const float4*)(lp + 8);
        v[0] = q0.x; v[1] = q0.y; v[2]  = q0.z; v[3]  = q0.w;
        v[4] = q1.x; v[5] = q1.y; v[6]  = q1.z; v[7]  = q1.w;
        v[8] = q2.x; v[9] = q2.y; v[10] = q2.z; v[11] = q2.w;
        int arg = 0; float best = v[0];
        #pragma unroll
        for (int c = 1; c < C; c++) if (v[c] > best) { best = v[c]; arg = c; }
        unsigned pres = __reduce_or_sync(0xffffffffu, 1u << arg);
        #pragma unroll
        for (int c = 0; c < C; c++) {
            #pragma unroll
            for (int o = 16; o > 0; o >>= 1)
                v[c] += __shfl_xor_sync(0xffffffffu, v[c], o);
        }
        if (lane == 0) {
            #pragma unroll
            for (int c = 0; c < C; c++) g_cpart[bid][c] = v[c];
            g_prespart[bid] = (int)pres;
        }
    }
    __syncthreads();

    float4 csum[8];
    #pragma unroll
    for (int j = 0; j < 8; j++) csum[j] = make_float4(0.f, 0.f, 0.f, 0.f);
    #pragma unroll
    for (int t = 0; t < 4; t++) {
        const int rr = w + 8 * t;
        const float* p = base + (size_t)rr * D;
        __half* ph = g_hi + (size_t)(r0 + rr) * D;
        unsigned char* p8h = g_h8 + (size_t)(r0 + rr) * D;
        unsigned char* p8l = g_l8 + (size_t)(r0 + rr) * D;
        float sq = 0.f;
        #pragma unroll
        for (int j = 0; j < 8; j++) {
            const int col = lane * 4 + 128 * j;
            float4 v = *(const float4*)(p + col);
            sq += v.x * v.x + v.y * v.y + v.z * v.z + v.w * v.w;
            csum[j].x += v.x; csum[j].y += v.y; csum[j].z += v.z; csum[j].w += v.w;
            __half h[4];
            float vv[4] = {v.x, v.y, v.z, v.w};
            uint32_t hp = 0, lp = 0;
            #pragma unroll
            for (int q = 0; q < 4; q++) {
                h[q] = __float2half_rn(vv[q]);
                float hf = __half2float(h[q]);
                float lf = vv[q] - hf;
                int qh = clamp127(__float2int_rn(hf * 16.f));
                int ql = clamp127(__float2int_rn(lf * 32768.f));
                hp |= ((uint32_t)qh & 0xFFu) << (8 * q);
                lp |= ((uint32_t)ql & 0xFFu) << (8 * q);
            }
            *(uint2*)(ph + col) = *(uint2*)h;
            *(uint32_t*)(p8h + col) = hp;
            *(uint32_t*)(p8l + col) = lp;
        }
        #pragma unroll
        for (int o = 16; o > 0; o >>= 1) sq += __shfl_xor_sync(0xffffffffu, sq, o);
        if (lane == 0) g_sq[r0 + rr] = sq;
    }
    #pragma unroll
    for (int j = 0; j < 8; j++) {
        const int col = lane * 4 + 128 * j;
        atomicAdd(&scol[col + 0], csum[j].x);
        atomicAdd(&scol[col + 1], csum[j].y);
        atomicAdd(&scol[col + 2], csum[j].z);
        atomicAdd(&scol[col + 3], csum[j].w);
    }
    __syncthreads();
    #pragma unroll
    for (int q = 0; q < 4; q++) {
        const int c = tid + 256 * q;
        g_colpart[bid][c] = scol[c];
    }
    __threadfence();
    __syncthreads();
    if (tid == 0) lastf = (atomicAdd(&g_pctr, 1) == 127) ? 1 : 0;
    __syncthreads();
    if (!lastf) return;

    if (tid < C) {
        float ss = 0.f, ts = 0.f;
        int sp = 0, tp = 0;
        for (int b = 0; b < 64; b++)   { ss += g_cpart[b][tid]; sp |= g_prespart[b]; }
        for (int b = 64; b < 128; b++) { ts += g_cpart[b][tid]; tp |= g_prespart[b]; }
        bool common = ((sp >> tid) & 1) && ((tp >> tid) & 1);
        g_fac[tid]     = (common && ss > 0.f) ?  1.f / ss : 0.f;
        g_fac[C + tid] = (common && ts > 0.f) ? -1.f / ts : 0.f;
    }
    double s = 0.0;
    for (int i = tid; i < NROWS; i += 256) s += (double)g_sq[i];
    dr[tid] = s;
    __syncthreads();
    for (int o = 128; o > 0; o >>= 1) {
        if (tid < o) dr[tid] += dr[tid + o];
        __syncthreads();
    }
    double sumsq = dr[0];
    __syncthreads();
    s = 0.0;
    for (int c = tid; c < D; c += 256) {
        float cs = 0.f;
        for (int b = 0; b < 128; b++) cs += g_colpart[b][c];
        s += (double)cs * (double)cs;
    }
    dr[tid] = s;
    __syncthreads();
    for (int o = 128; o > 0; o >>= 1) {
        if (tid < o) dr[tid] += dr[tid + o];
        __syncthreads();
    }
    if (tid == 0) {
        const double n = (double)NROWS;
        double sum_l2 = 2.0 * n * sumsq - 2.0 * dr[0];
        double bw = sum_l2 / (n * n - n) / 4.0;
        g_coef = (float)(-1.0 / (16.0 * bw * 0.6931471805599453));
        g_loss = 0.0;
        g_tilectr = 0;
        g_donectr = 0;
        g_pctr = 0;
    }
}

// ============== launch 1: persistent mixed fp16/int8 MMA + MMD + output
__global__ __launch_bounds__(256, 2) void k_mmd(const float* __restrict__ sl,
                                                const float* __restrict__ tl,
                                                float* __restrict__ out) {
    extern __shared__ __align__(16) unsigned char sm[];
    float* zB  = (float*)(sm + OFF_ZB);
    float* sqB = (float*)(sm + OFF_SQB);
    __shared__ float red[8];
    __shared__ float s_fac[2 * C];
    __shared__ int s_tile;

    const int tid = threadIdx.x, wid = tid >> 5, lane = tid & 31;
    const int wm = wid >> 1, wn = wid & 1;           // warp grid 4m x 2n (warp = 32x32)
    const int gq = lane >> 2, gr = lane & 3;
    const uint32_t smU = s2u(sm);

    if (tid < 2 * C) s_fac[tid] = g_fac[tid];

    // ldmatrix lane offsets (bytes, within array)
    const uint32_t aoffH = (((uint32_t)(wm * 32 + (lane & 15))) * RSTR + (lane >> 4) * 8) * 2;
    const uint32_t boffH = (((uint32_t)(wn * 32 + (lane & 7) + ((lane >> 4) * 8))) * RSTR
                           + ((lane >> 3) & 1) * 8) * 2;
    const uint32_t aoff8 = (uint32_t)(wm * 32 + (lane & 15)) * R8 + (lane >> 4) * 16;
    const uint32_t boff8 = (uint32_t)(wn * 32 + (lane & 15)) * R8 + (lane >> 4) * 16;

    while (true) {
        if (tid == 0) s_tile = atomicAdd(&g_tilectr, 1);
        __syncthreads();
        const int T = s_tile;
        if (T >= NTILES2) break;

        const int t2 = T >> 1, half = T & 1;
        int L = t2, bi = 0;
        while (L >= NT - bi) { L -= NT - bi; bi++; }
        const int bj = bi + L;
        const int rowA = bi * BM, rowB = bj * BM + half * BN;
        const size_t gA = (size_t)rowA * D, gB = (size_t)rowB * D;

    #define STAGE(buf, c) do {                                                           \
        const uint32_t bo = (buf) * BUFSZ;                                               \
        const size_t ko = (size_t)(c) * KCH;                                             \
        CP_ASYNC16(smU + bo + OFF_AHI + ((tid >> 2) * RSTR + (tid & 3) * 8) * 2,         \
                   g_hi + gA + (size_t)(tid >> 2) * D + ko + (tid & 3) * 8);             \
        CP_ASYNC16(smU + bo + OFF_AHI + (((tid >> 2) + 64) * RSTR + (tid & 3) * 8) * 2,  \
                   g_hi + gA + (size_t)((tid >> 2) + 64) * D + ko + (tid & 3) * 8);      \
        CP_ASYNC16(smU + bo + OFF_BHI + ((tid >> 2) * RSTR + (tid & 3) * 8) * 2,         \
                   g_hi + gB + (size_t)(tid >> 2) * D + ko + (tid & 3) * 8);             \
        CP_ASYNC16(smU + bo + OFF_A8H + (tid >> 1) * R8 + (tid & 1) * 16,                \
                   g_h8 + gA + (size_t)(tid >> 1) * D + ko + (tid & 1) * 16);            \
        CP_ASYNC16(smU + bo + OFF_A8L + (tid >> 1) * R8 + (tid & 1) * 16,                \
                   g_l8 + gA + (size_t)(tid >> 1) * D + ko + (tid & 1) * 16);            \
        if (tid < 128)                                                                   \
            CP_ASYNC16(smU + bo + OFF_B8H + (tid >> 1) * R8 + (tid & 1) * 16,            \
                       g_h8 + gB + (size_t)(tid >> 1) * D + ko + (tid & 1) * 16);        \
        else                                                                             \
            CP_ASYNC16(smU + bo + OFF_B8L + ((tid - 128) >> 1) * R8 + (tid & 1) * 16,    \
                       g_l8 + gB + (size_t)((tid - 128) >> 1) * D + ko + (tid & 1) * 16);\
        CP_COMMIT();                                                                     \
    } while (0)

        STAGE(0, 0);

        for (int t = tid; t < BN * C; t += 256) {
            const int r = rowB + t / C, c = t % C;
            zB[t] = (r < BHALF) ? sl[(size_t)r * C + c] * s_fac[c]
                                : tl[(size_t)(r - BHALF) * C + c] * s_fac[C + c];
        }
        if (tid < BN) sqB[tid] = g_sq[rowB + tid];

        float accf[2][4][4];
        int   acci[2][4][4];
        #pragma unroll
        for (int m = 0; m < 2; m++)
            #pragma unroll
            for (int n = 0; n < 4; n++)
                #pragma unroll
                for (int r = 0; r < 4; r++) { accf[m][n][r] = 0.f; acci[m][n][r] = 0; }

        for (int c = 0; c < NCH; c++) {
            const int buf = c & 1;
            CP_WAIT0();
            __syncthreads();
            if (c + 1 < NCH) STAGE(buf ^ 1, c + 1);

            const uint32_t bo = (uint32_t)buf * BUFSZ;
            const uint32_t aHi = smU + bo + OFF_AHI + aoffH;
            const uint32_t bHi = smU + bo + OFF_BHI + boffH;
            const uint32_t a8H = smU + bo + OFF_A8H + aoff8;
            const uint32_t a8L = smU + bo + OFF_A8L + aoff8;
            const uint32_t b8H = smU + bo + OFF_B8H + boff8;
            const uint32_t b8L = smU + bo + OFF_B8L + boff8;

            // ---- fp16 hi*hi ----
            #pragma unroll
            for (int ks = 0; ks < 2; ks++) {
                const uint32_t kso = ks * 32;
                uint32_t ah[2][4], bh0[4], bh1[4];
                LDSM4(ah[0], aHi + kso);
                LDSM4(ah[1], aHi + kso + 16 * RSTR * 2);
                LDSM4(bh0, bHi + kso);
                LDSM4(bh1, bHi + kso + 16 * RSTR * 2);
                #pragma unroll
                for (int m = 0; m < 2; m++) {
                    mma_f16(accf[m][0], ah[m], bh0[0], bh0[1]);
                    mma_f16(accf[m][1], ah[m], bh0[2], bh0[3]);
                    mma_f16(accf[m][2], ah[m], bh1[0], bh1[1]);
                    mma_f16(accf[m][3], ah[m], bh1[2], bh1[3]);
                }
            }
            // ---- int8 cross terms: h8*l8' + l8*h8' (shared int32 acc) ----
            {
                uint32_t a8h[2][4], a8l[2][4], b8h0[4], b8h1[4], b8l0[4], b8l1[4];
                LDSM4(a8h[0], a8H);
                LDSM4(a8h[1], a8H + 16 * R8);
                LDSM4(a8l[0], a8L);
                LDSM4(a8l[1], a8L + 16 * R8);
                LDSM4(b8h0, b8H);
                LDSM4(b8h1, b8H + 16 * R8);
                LDSM4(b8l0, b8L);
                LDSM4(b8l1, b8L + 16 * R8);
                #pragma unroll
                for (int m = 0; m < 2; m++) {
                    mma_s8(acci[m][0], a8h[m], b8l0[0], b8l0[2]);
                    mma_s8(acci[m][0], a8l[m], b8h0[0], b8h0[2]);
                    mma_s8(acci[m][1], a8h[m], b8l0[1], b8l0[3]);
                    mma_s8(acci[m][1], a8l[m], b8h0[1], b8h0[3]);
                    mma_s8(acci[m][2], a8h[m], b8l1[0], b8l1[2]);
                    mma_s8(acci[m][2], a8l[m], b8h1[0], b8h1[2]);
                    mma_s8(acci[m][3], a8h[m], b8l1[1], b8l1[3]);
                    mma_s8(acci[m][3], a8l[m], b8h1[1], b8h1[3]);
                }
            }
        }

        // ---- epilogue ----
        const float coef = g_coef;
        float lsum = 0.f;
        #pragma unroll
        for (int m = 0; m < 2; m++) {
            #pragma unroll
            for (int h = 0; h < 2; h++) {
                const int i = rowA + wm * 32 + m * 16 + gq + 8 * h;
                const float sqi = g_sq[i];
                const float* zp = (i < BHALF) ? sl + (size_t)i * C
                                              : tl + (size_t)(i - BHALF) * C;
                const int fo = (i < BHALF) ? 0 : C;
                float zi[C];
                {
                    float4 q0 = *(const float4*)zp;
                    float4 q1 = *(const float4*)(zp + 4);
                    float4 q2 = *(const float4*)(zp + 8);
                    zi[0]  = q0.x * s_fac[fo + 0];  zi[1]  = q0.y * s_fac[fo + 1];
                    zi[2]  = q0.z * s_fac[fo + 2];  zi[3]  = q0.w * s_fac[fo + 3];
                    zi[4]  = q1.x * s_fac[fo + 4];  zi[5]  = q1.y * s_fac[fo + 5];
                    zi[6]  = q1.z * s_fac[fo + 6];  zi[7]  = q1.w * s_fac[fo + 7];
                    zi[8]  = q2.x * s_fac[fo + 8];  zi[9]  = q2.y * s_fac[fo + 9];
                    zi[10] = q2.z * s_fac[fo + 10]; zi[11] = q2.w * s_fac[fo + 11];
                }
                #pragma unroll
                for (int n = 0; n < 4; n++) {
                    #pragma unroll
                    for (int p = 0; p < 2; p++) {
                        const int j = wn * 32 + n * 8 + 2 * gr + p;
                        const float gv = accf[m][n][2 * h + p]
                                       + (float)acci[m][n][2 * h + p] * SCALE8;
                        float l2 = fmaxf(fmaf(-2.f, gv, sqi + sqB[j]), 0.f);
                        float e;
                        asm("ex2.approx.ftz.f32 %0, %1;" : "=f"(e) : "f"(l2 * coef));
                        float e2 = e * e, e4 = e2 * e2, e8 = e4 * e4, e16 = e8 * e8;
                        float ks5 = e + e2 + e4 + e8 + e16;
                        float w = 0.f;
                        #pragma unroll
                        for (int cc = 0; cc < C; cc++) w = fmaf(zi[cc], zB[j * C + cc], w);
                        lsum = fmaf(w, ks5, lsum);
                    }
                }
            }
        }
        if (bi != bj) lsum *= 2.f;

        #pragma unroll
        for (int o = 16; o > 0; o >>= 1) lsum += __shfl_xor_sync(0xffffffffu, lsum, o);
        if (lane == 0) red[wid] = lsum;
        __syncthreads();
        if (tid == 0) {
            float s = 0.f;
            #pragma unroll
            for (int w = 0; w < 8; w++) s += red[w];
            atomicAdd(&g_loss, (double)s);
        }
    }

    if (tid == 0) {
        __threadfence();
        int d = atomicAdd(&g_donectr, 1);
        if (d == (int)gridDim.x - 1) {
            float f = (float)(g_loss / 12.0);
            if (!isfinite(f)) f = 0.f;
            out[0] = f;
        }
    }
}

// ================================================================ launch
extern "C" void kernel_launch(void* const* d_in, const int* in_sizes, int n_in,
                              void* d_out, int out_size) {
    const float* src = (const float*)d_in[0];
    const float* tgt = (const float*)d_in[1];
    const float* sl  = (const float*)d_in[2];
    const float* tl  = (const float*)d_in[3];
    float* out = (float*)d_out;

    cudaFuncSetAttribute(k_mmd, cudaFuncAttributeMaxDynamicSharedMemorySize, SMEM_REQ);

    k_prep<<<128, 256>>>(src, tgt, sl, tl);          // launch 0
    k_mmd<<<NPERS, 256, SMEM_REQ>>>(sl, tl, out);    // launch 1
}